// round 6
// baseline (speedup 1.0000x reference)
#include <cuda_runtime.h>
#include <cuda_bf16.h>
#include <math.h>
#include <stdint.h>

// Problem constants: B=4, T=2048, C=768, H=12, D=64
#define Bv 4
#define Tv 2048
#define Cv 768
#define Hv 12
#define Dv 64
#define C3v (3 * Cv)     // 2304
#define Mv (Bv * Tv)     // 8192

// ---------------- device scratch (no allocation allowed) -------------------
__device__ float g_qkv[(size_t)Mv * C3v];
__device__ __nv_bfloat16 g_x_hi[(size_t)Mv * Cv];
__device__ __nv_bfloat16 g_x_lo[(size_t)Mv * Cv];
__device__ __nv_bfloat16 g_wA_hi[(size_t)C3v * Cv];
__device__ __nv_bfloat16 g_wA_lo[(size_t)C3v * Cv];
__device__ __nv_bfloat16 g_wP_hi[(size_t)Cv * Cv];
__device__ __nv_bfloat16 g_wP_lo[(size_t)Cv * Cv];
__device__ __nv_bfloat16 g_y_hi[(size_t)Mv * Cv];
__device__ __nv_bfloat16 g_y_lo[(size_t)Mv * Cv];

// ---------------------------------------------------------------------------
__device__ __forceinline__ void mma16816(float* c, const uint32_t* a,
                                         uint32_t b0, uint32_t b1) {
    asm volatile(
        "mma.sync.aligned.m16n8k16.row.col.f32.bf16.bf16.f32 "
        "{%0,%1,%2,%3}, {%4,%5,%6,%7}, {%8,%9}, {%0,%1,%2,%3};"
        : "+f"(c[0]), "+f"(c[1]), "+f"(c[2]), "+f"(c[3])
        : "r"(a[0]), "r"(a[1]), "r"(a[2]), "r"(a[3]), "r"(b0), "r"(b1));
}

__device__ __forceinline__ uint32_t smem_u32(const void* p) {
    uint32_t a;
    asm("{ .reg .u64 t; cvta.to.shared.u64 t, %1; cvt.u32.u64 %0, t; }" : "=r"(a) : "l"(p));
    return a;
}
#define CP16(dst, src) \
    asm volatile("cp.async.cg.shared.global [%0], [%1], 16;" :: "r"(dst), "l"(src))
#define CP_COMMIT() asm volatile("cp.async.commit_group;" ::: "memory")
#define CP_WAIT2()  asm volatile("cp.async.wait_group 2;" ::: "memory")
#define CP_WAIT1()  asm volatile("cp.async.wait_group 1;" ::: "memory")
#define CP_WAIT0()  asm volatile("cp.async.wait_group 0;" ::: "memory")

__device__ __forceinline__ uint32_t pack_bf(float a, float b) {
    __nv_bfloat162 t;
    t.x = __float2bfloat16(a);
    t.y = __float2bfloat16(b);
    return *(uint32_t*)&t;
}
__device__ __forceinline__ void split_pack(float a, float b, uint32_t& hi, uint32_t& lo) {
    float ah = __bfloat162float(__float2bfloat16(a));
    float bh = __bfloat162float(__float2bfloat16(b));
    hi = pack_bf(ah, bh);
    lo = pack_bf(a - ah, b - bh);
}

// ---------------------------------------------------------------------------
__global__ void split_kernel(const float* __restrict__ in,
                             __nv_bfloat16* __restrict__ hi,
                             __nv_bfloat16* __restrict__ lo, int n) {
    int i = (blockIdx.x * 256 + threadIdx.x) * 4;
    if (i >= n) return;
    float4 v = *(const float4*)(in + i);
    uint32_t h0, l0, h1, l1;
    split_pack(v.x, v.y, h0, l0);
    split_pack(v.z, v.w, h1, l1);
    *(uint32_t*)(hi + i)     = h0;
    *(uint32_t*)(hi + i + 2) = h1;
    *(uint32_t*)(lo + i)     = l0;
    *(uint32_t*)(lo + i + 2) = l1;
}

__global__ void transpose_split(const float* __restrict__ w,
                                __nv_bfloat16* __restrict__ thi,
                                __nv_bfloat16* __restrict__ tlo, int K, int N) {
    __shared__ float st[32][33];
    const int n0 = blockIdx.x * 32, k0 = blockIdx.y * 32;
    const int tx = threadIdx.x, ty = threadIdx.y;          // (32, 8)
    #pragma unroll
    for (int i = 0; i < 4; i++)
        st[ty + 8 * i][tx] = w[(size_t)(k0 + ty + 8 * i) * N + n0 + tx];
    __syncthreads();
    #pragma unroll
    for (int i = 0; i < 4; i++) {
        float f = st[tx][ty + 8 * i];
        __nv_bfloat16 hh = __float2bfloat16(f);
        __nv_bfloat16 ll = __float2bfloat16(f - __bfloat162float(hh));
        size_t o = (size_t)(n0 + ty + 8 * i) * K + k0 + tx;
        thi[o] = hh;
        tlo[o] = ll;
    }
}

// ---------------------------------------------------------------------------
// Tensor-core bf16-split GEMM, 3-stage cp.async pipeline.
// ---------------------------------------------------------------------------
#define GRS 40
#define GT_BYTES 10240                 // 128 * 40 * 2
#define GB_OFF   (6 * GT_BYTES)        // B region after 3 stages x 2 parts of A
#define G_SMEM   (12 * GT_BYTES)       // 122880

__global__ __launch_bounds__(256)
void gemm_mma(const __nv_bfloat16* __restrict__ Ahi, const __nv_bfloat16* __restrict__ Alo,
              const __nv_bfloat16* __restrict__ Bhi, const __nv_bfloat16* __restrict__ Blo,
              const float* __restrict__ bias, float* __restrict__ Cmat,
              int N, int K) {
    extern __shared__ __align__(16) char gsm[];
    const uint32_t sb = smem_u32(gsm);

    const int tid = threadIdx.x;
    const int wid = tid >> 5, lane = tid & 31;
    const int g = lane >> 2, tig = lane & 3;
    const int bx = blockIdx.x, by = blockIdx.y;
    const int wm = (wid & 3) * 32;
    const int wn = (wid >> 2) * 64;

    const int lrow = tid >> 2;                  // 0..63
    const int lc8  = (tid & 3) * 8;             // 0,8,16,24

    float acc[2][8][4];
    #pragma unroll
    for (int mt = 0; mt < 2; mt++)
        #pragma unroll
        for (int nt = 0; nt < 8; nt++)
            #pragma unroll
            for (int j = 0; j < 4; j++) acc[mt][nt][j] = 0.f;

    const int nCh = K >> 5;

    auto load_chunk = [&](int c, int s) {
        const int k0 = c << 5;
        #pragma unroll
        for (int i = 0; i < 2; i++) {
            const int r = lrow + i * 64;
            const size_t ga = (size_t)(by * 128 + r) * K + k0 + lc8;
            const size_t gb = (size_t)(bx * 128 + r) * K + k0 + lc8;
            const uint32_t ro = (uint32_t)(r * (GRS * 2) + lc8 * 2);
            CP16(sb + (s * 2 + 0) * GT_BYTES + ro,          Ahi + ga);
            CP16(sb + (s * 2 + 1) * GT_BYTES + ro,          Alo + ga);
            CP16(sb + GB_OFF + (s * 2 + 0) * GT_BYTES + ro, Bhi + gb);
            CP16(sb + GB_OFF + (s * 2 + 1) * GT_BYTES + ro, Blo + gb);
        }
    };

    load_chunk(0, 0); CP_COMMIT();
    load_chunk(1, 1); CP_COMMIT();

    int s = 0;
    for (int c = 0; c < nCh; c++) {
        if (c + 2 < nCh) load_chunk(c + 2, (s + 2) % 3);
        CP_COMMIT();                   // always commit (empty groups at tail)
        CP_WAIT2();                    // chunk c's group complete
        __syncthreads();

        #pragma unroll
        for (int pass = 0; pass < 3; pass++) {
            const int pa = (pass == 2) ? 1 : 0;
            const int pb = (pass == 1) ? 1 : 0;
            const __nv_bfloat16 (*Asp)[GRS] =
                (const __nv_bfloat16(*)[GRS])(gsm + (s * 2 + pa) * GT_BYTES);
            const __nv_bfloat16 (*Bsp)[GRS] =
                (const __nv_bfloat16(*)[GRS])(gsm + GB_OFF + (s * 2 + pb) * GT_BYTES);
            #pragma unroll
            for (int ks = 0; ks < 2; ks++) {
                const int kc = ks * 16 + tig * 2;
                uint32_t afr[2][4];
                #pragma unroll
                for (int mt = 0; mt < 2; mt++) {
                    const int r0 = wm + mt * 16 + g;
                    afr[mt][0] = *(const uint32_t*)&Asp[r0][kc];
                    afr[mt][1] = *(const uint32_t*)&Asp[r0 + 8][kc];
                    afr[mt][2] = *(const uint32_t*)&Asp[r0][kc + 8];
                    afr[mt][3] = *(const uint32_t*)&Asp[r0 + 8][kc + 8];
                }
                #pragma unroll
                for (int nt = 0; nt < 8; nt++) {
                    const int n0 = wn + nt * 8 + g;
                    const uint32_t b0 = *(const uint32_t*)&Bsp[n0][kc];
                    const uint32_t b1 = *(const uint32_t*)&Bsp[n0][kc + 8];
                    mma16816(acc[0][nt], afr[0], b0, b1);
                    mma16816(acc[1][nt], afr[1], b0, b1);
                }
            }
        }
        __syncthreads();
        s = (s + 1) % 3;
    }

    #pragma unroll
    for (int mt = 0; mt < 2; mt++) {
        #pragma unroll
        for (int nt = 0; nt < 8; nt++) {
            const int rg = by * 128 + wm + mt * 16 + g;
            const int cg = bx * 128 + wn + nt * 8 + tig * 2;
            const float bs0 = __ldg(bias + cg), bs1 = __ldg(bias + cg + 1);
            float2 v0, v1;
            v0.x = acc[mt][nt][0] + bs0;
            v0.y = acc[mt][nt][1] + bs1;
            v1.x = acc[mt][nt][2] + bs0;
            v1.y = acc[mt][nt][3] + bs1;
            *(float2*)(Cmat + (size_t)rg * N + cg)       = v0;
            *(float2*)(Cmat + (size_t)(rg + 8) * N + cg) = v1;
        }
    }
}

// ---------------------------------------------------------------------------
// Tensor-core causal flash attention, cp.async double-buffered K/V staging.
// Block: 256 thr (8 warps), 128 q rows; warp = 16 rows x full D=64.
// ---------------------------------------------------------------------------
#define AKS 66                    // bf16 buffers row stride (33 words = conflict-free)
#define VSTW 68                   // fp32 staging row stride (272B, 16B-mult)
#define ST_BYTES (64 * VSTW * 4)  // 17408 per staging tile
#define A_OFF_KST 0                           // 2 stages K fp32
#define A_OFF_VST (2 * ST_BYTES)              // 2 stages V fp32
#define A_OFF_KSH (4 * ST_BYTES)              // 69632
#define A_OFF_KSL (A_OFF_KSH + 64 * AKS * 2)  // +8448
#define A_OFF_VTH (A_OFF_KSL + 64 * AKS * 2)
#define A_OFF_VTL (A_OFF_VTH + 64 * AKS * 2)
#define A_SMEM    (A_OFF_VTL + 64 * AKS * 2)  // 103424

__global__ __launch_bounds__(256)
void attn_mma(const float* __restrict__ qkv,
              __nv_bfloat16* __restrict__ yhi, __nv_bfloat16* __restrict__ ylo) {
    extern __shared__ __align__(16) char sm[];
    const uint32_t sbase = smem_u32(sm);
    float (*Kst)[64][VSTW] = (float(*)[64][VSTW])(sm + A_OFF_KST);
    float (*Vst)[64][VSTW] = (float(*)[64][VSTW])(sm + A_OFF_VST);
    __nv_bfloat16 (*Ksh)[AKS] = (__nv_bfloat16(*)[AKS])(sm + A_OFF_KSH);
    __nv_bfloat16 (*Ksl)[AKS] = (__nv_bfloat16(*)[AKS])(sm + A_OFF_KSL);
    __nv_bfloat16 (*Vth)[AKS] = (__nv_bfloat16(*)[AKS])(sm + A_OFF_VTH);
    __nv_bfloat16 (*Vtl)[AKS] = (__nv_bfloat16(*)[AKS])(sm + A_OFF_VTL);

    const int qt = (gridDim.x - 1) - blockIdx.x;   // heavy blocks first
    const int h  = blockIdx.y;
    const int b  = blockIdx.z;
    const int tid = threadIdx.x;
    const int wid = tid >> 5, lane = tid & 31;
    const int g = lane >> 2, tig = lane & 3;

    const int qr0 = qt * 128;
    const int row0 = qr0 + wid * 16 + g;
    const float* base = qkv + (size_t)b * Tv * C3v;

    // async-load raw fp32 K+V tile for kv block kvb into stage s
    auto load_kv = [&](int kvb, int s) {
        const int kv0 = kvb * 64;
        #pragma unroll
        for (int i = 0; i < 4; i++) {
            const int u = tid + i * 256;
            const int r = u >> 4, c4 = (u & 15) * 4;
            const float* rowp = base + (size_t)(kv0 + r) * C3v + h * Dv + c4;
            CP16(sbase + A_OFF_KST + s * ST_BYTES + (r * VSTW + c4) * 4, rowp + Cv);
            CP16(sbase + A_OFF_VST + s * ST_BYTES + (r * VSTW + c4) * 4, rowp + 2 * Cv);
        }
    };

    // Q fragments (scaled), hi/lo split
    uint32_t qh[4][4], ql[4][4];
    {
        const float sc = 0.125f;
        #pragma unroll
        for (int ks = 0; ks < 4; ks++) {
            const int kc = ks * 16 + tig * 2;
            #pragma unroll
            for (int j = 0; j < 4; j++) {
                const int rr = (j & 1) ? row0 + 8 : row0;
                const int cc = kc + ((j >> 1) ? 8 : 0);
                float2 v = *(const float2*)(base + (size_t)rr * C3v + h * Dv + cc);
                split_pack(v.x * sc, v.y * sc, qh[ks][j], ql[ks][j]);
            }
        }
    }

    float acc_o[8][4];
    #pragma unroll
    for (int nt = 0; nt < 8; nt++)
        #pragma unroll
        for (int j = 0; j < 4; j++) acc_o[nt][j] = 0.f;
    float m0 = -INFINITY, m1 = -INFINITY, l0 = 0.f, l1 = 0.f;

    const int nkv = (qr0 >> 6) + 2;
    load_kv(0, 0); CP_COMMIT();

    for (int kvb = 0; kvb < nkv; kvb++) {
        const int kv0 = kvb * 64;
        const int s = kvb & 1;
        if (kvb + 1 < nkv) { load_kv(kvb + 1, s ^ 1); CP_COMMIT(); CP_WAIT1(); }
        else CP_WAIT0();
        __syncthreads();   // staging s landed; previous iter's bf16 buffers consumed

        // convert K -> Ksh/Ksl   (thread: row cr, 16 cols)
        {
            const int cr = tid >> 2, cq = (tid & 3) * 16;
            #pragma unroll
            for (int j = 0; j < 4; j++) {
                float4 v = *(const float4*)&Kst[s][cr][cq + j * 4];
                uint32_t h0, lo0, h1, lo1;
                split_pack(v.x, v.y, h0, lo0);
                split_pack(v.z, v.w, h1, lo1);
                *(uint32_t*)&Ksh[cr][cq + j * 4]     = h0;
                *(uint32_t*)&Ksh[cr][cq + j * 4 + 2] = h1;
                *(uint32_t*)&Ksl[cr][cq + j * 4]     = lo0;
                *(uint32_t*)&Ksl[cr][cq + j * 4 + 2] = lo1;
            }
        }
        // transpose V -> Vth/Vtl (thread: col d, 16 rows)
        {
            const int d = tid & 63, kq = (tid >> 6) * 16;
            #pragma unroll
            for (int i = 0; i < 16; i += 2) {
                float f0 = Vst[s][kq + i][d];
                float f1 = Vst[s][kq + i + 1][d];
                uint32_t hh, lo;
                split_pack(f0, f1, hh, lo);
                *(uint32_t*)&Vth[d][kq + i] = hh;
                *(uint32_t*)&Vtl[d][kq + i] = lo;
            }
        }
        __syncthreads();

        if (kv0 <= qr0 + wid * 16 + 15) {
            float s_[8][4];
            #pragma unroll
            for (int nt = 0; nt < 8; nt++)
                #pragma unroll
                for (int j = 0; j < 4; j++) s_[nt][j] = 0.f;

            #pragma unroll
            for (int pass = 0; pass < 3; pass++) {
                #pragma unroll
                for (int ks = 0; ks < 4; ks++) {
                    const uint32_t* A = (pass == 2) ? ql[ks] : qh[ks];
                    const __nv_bfloat16 (*Bsrc)[AKS] = (pass == 1) ? Ksl : Ksh;
                    const int kc = ks * 16 + tig * 2;
                    #pragma unroll
                    for (int nt = 0; nt < 8; nt++) {
                        const int n0 = nt * 8 + g;
                        const uint32_t b0 = *(const uint32_t*)&Bsrc[n0][kc];
                        const uint32_t b1 = *(const uint32_t*)&Bsrc[n0][kc + 8];
                        mma16816(s_[nt], A, b0, b1);
                    }
                }
            }

            float rmax0 = -INFINITY, rmax1 = -INFINITY;
            #pragma unroll
            for (int nt = 0; nt < 8; nt++) {
                const int colb = kv0 + nt * 8 + tig * 2;
                #pragma unroll
                for (int j = 0; j < 2; j++) {
                    if (colb + j > row0)     s_[nt][j]     = -INFINITY;
                    if (colb + j > row0 + 8) s_[nt][2 + j] = -INFINITY;
                    rmax0 = fmaxf(rmax0, s_[nt][j]);
                    rmax1 = fmaxf(rmax1, s_[nt][2 + j]);
                }
            }
            rmax0 = fmaxf(rmax0, __shfl_xor_sync(0xffffffff, rmax0, 1));
            rmax0 = fmaxf(rmax0, __shfl_xor_sync(0xffffffff, rmax0, 2));
            rmax1 = fmaxf(rmax1, __shfl_xor_sync(0xffffffff, rmax1, 1));
            rmax1 = fmaxf(rmax1, __shfl_xor_sync(0xffffffff, rmax1, 2));

            const float mn0 = fmaxf(m0, rmax0);
            const float mn1 = fmaxf(m1, rmax1);
            const float cr0 = __expf(m0 - mn0);
            const float cr1 = __expf(m1 - mn1);
            l0 *= cr0; l1 *= cr1;
            #pragma unroll
            for (int nt = 0; nt < 8; nt++) {
                acc_o[nt][0] *= cr0; acc_o[nt][1] *= cr0;
                acc_o[nt][2] *= cr1; acc_o[nt][3] *= cr1;
            }
            m0 = mn0; m1 = mn1;

            uint32_t ph[4][4], pl[4][4];
            float rs0 = 0.f, rs1 = 0.f;
            #pragma unroll
            for (int kt = 0; kt < 4; kt++) {
                float p00, p01, p10, p11;
                p00 = __expf(s_[2 * kt][0] - mn0);
                p01 = __expf(s_[2 * kt][1] - mn0);
                p10 = __expf(s_[2 * kt][2] - mn1);
                p11 = __expf(s_[2 * kt][3] - mn1);
                rs0 += p00 + p01; rs1 += p10 + p11;
                split_pack(p00, p01, ph[kt][0], pl[kt][0]);
                split_pack(p10, p11, ph[kt][1], pl[kt][1]);
                p00 = __expf(s_[2 * kt + 1][0] - mn0);
                p01 = __expf(s_[2 * kt + 1][1] - mn0);
                p10 = __expf(s_[2 * kt + 1][2] - mn1);
                p11 = __expf(s_[2 * kt + 1][3] - mn1);
                rs0 += p00 + p01; rs1 += p10 + p11;
                split_pack(p00, p01, ph[kt][2], pl[kt][2]);
                split_pack(p10, p11, ph[kt][3], pl[kt][3]);
            }
            rs0 += __shfl_xor_sync(0xffffffff, rs0, 1);
            rs0 += __shfl_xor_sync(0xffffffff, rs0, 2);
            rs1 += __shfl_xor_sync(0xffffffff, rs1, 1);
            rs1 += __shfl_xor_sync(0xffffffff, rs1, 2);
            l0 += rs0; l1 += rs1;

            #pragma unroll
            for (int pass = 0; pass < 3; pass++) {
                const __nv_bfloat16 (*Bsrc)[AKS] = (pass == 1) ? Vtl : Vth;
                #pragma unroll
                for (int kt = 0; kt < 4; kt++) {
                    const uint32_t* A = (pass == 2) ? pl[kt] : ph[kt];
                    const int kc = kt * 16 + tig * 2;
                    #pragma unroll
                    for (int nt = 0; nt < 8; nt++) {
                        const int n0 = nt * 8 + g;
                        const uint32_t b0 = *(const uint32_t*)&Bsrc[n0][kc];
                        const uint32_t b1 = *(const uint32_t*)&Bsrc[n0][kc + 8];
                        mma16816(acc_o[nt], A, b0, b1);
                    }
                }
            }
        }
        __syncthreads();
    }

    const float i0 = 1.f / l0, i1 = 1.f / l1;
    #pragma unroll
    for (int nt = 0; nt < 8; nt++) {
        const int d = nt * 8 + tig * 2;
        const size_t o0 = ((size_t)b * Tv + row0) * Cv + h * Dv + d;
        const size_t o1 = o0 + (size_t)8 * Cv;
        uint32_t hh, lo;
        split_pack(acc_o[nt][0] * i0, acc_o[nt][1] * i0, hh, lo);
        *(uint32_t*)(yhi + o0) = hh;
        *(uint32_t*)(ylo + o0) = lo;
        split_pack(acc_o[nt][2] * i1, acc_o[nt][3] * i1, hh, lo);
        *(uint32_t*)(yhi + o1) = hh;
        *(uint32_t*)(ylo + o1) = lo;
    }
}

// ---------------------------------------------------------------------------
extern "C" void kernel_launch(void* const* d_in, const int* in_sizes, int n_in,
                              void* d_out, int out_size) {
    const float* x      = (const float*)d_in[0];
    const float* w_attn = (const float*)d_in[1];
    const float* b_attn = (const float*)d_in[2];
    const float* w_proj = (const float*)d_in[3];
    const float* b_proj = (const float*)d_in[4];
    float* out = (float*)d_out;

    float* qkv; __nv_bfloat16 *xh, *xl, *wAh, *wAl, *wPh, *wPl, *yh, *yl;
    cudaGetSymbolAddress((void**)&qkv, g_qkv);
    cudaGetSymbolAddress((void**)&xh, g_x_hi);  cudaGetSymbolAddress((void**)&xl, g_x_lo);
    cudaGetSymbolAddress((void**)&wAh, g_wA_hi); cudaGetSymbolAddress((void**)&wAl, g_wA_lo);
    cudaGetSymbolAddress((void**)&wPh, g_wP_hi); cudaGetSymbolAddress((void**)&wPl, g_wP_lo);
    cudaGetSymbolAddress((void**)&yh, g_y_hi);  cudaGetSymbolAddress((void**)&yl, g_y_lo);

    cudaFuncSetAttribute(gemm_mma, cudaFuncAttributeMaxDynamicSharedMemorySize, G_SMEM);
    cudaFuncSetAttribute(attn_mma, cudaFuncAttributeMaxDynamicSharedMemorySize, A_SMEM);

    const int nx = Mv * Cv;
    split_kernel<<<(nx / 4 + 255) / 256, 256>>>(x, xh, xl, nx);
    transpose_split<<<dim3(C3v / 32, Cv / 32), dim3(32, 8)>>>(w_attn, wAh, wAl, Cv, C3v);
    transpose_split<<<dim3(Cv / 32, Cv / 32), dim3(32, 8)>>>(w_proj, wPh, wPl, Cv, Cv);

    gemm_mma<<<dim3(C3v / 128, Mv / 128), 256, G_SMEM>>>(xh, xl, wAh, wAl, b_attn, qkv, C3v, Cv);
    attn_mma<<<dim3(Tv / 128, Hv, Bv), 256, A_SMEM>>>(qkv, yh, yl);
    gemm_mma<<<dim3(Cv / 128, Mv / 128), 256, G_SMEM>>>(yh, yl, wPh, wPl, b_proj, out, Cv, Cv);
}

// round 7
// speedup vs baseline: 1.3033x; 1.3033x over previous
#include <cuda_runtime.h>
#include <cuda_bf16.h>
#include <math.h>
#include <stdint.h>

// Problem constants: B=4, T=2048, C=768, H=12, D=64
#define Bv 4
#define Tv 2048
#define Cv 768
#define Hv 12
#define Dv 64
#define C3v (3 * Cv)     // 2304
#define Mv (Bv * Tv)     // 8192

// ---------------- device scratch (no allocation allowed) -------------------
__device__ float g_qkv[(size_t)Mv * C3v];
__device__ __nv_bfloat16 g_x_hi[(size_t)Mv * Cv];
__device__ __nv_bfloat16 g_x_lo[(size_t)Mv * Cv];
__device__ __nv_bfloat16 g_wA_hi[(size_t)C3v * Cv];
__device__ __nv_bfloat16 g_wA_lo[(size_t)C3v * Cv];
__device__ __nv_bfloat16 g_wP_hi[(size_t)Cv * Cv];
__device__ __nv_bfloat16 g_wP_lo[(size_t)Cv * Cv];
__device__ __nv_bfloat16 g_y_hi[(size_t)Mv * Cv];
__device__ __nv_bfloat16 g_y_lo[(size_t)Mv * Cv];

// ---------------------------------------------------------------------------
__device__ __forceinline__ void mma16816(float* c, const uint32_t* a,
                                         uint32_t b0, uint32_t b1) {
    asm volatile(
        "mma.sync.aligned.m16n8k16.row.col.f32.bf16.bf16.f32 "
        "{%0,%1,%2,%3}, {%4,%5,%6,%7}, {%8,%9}, {%0,%1,%2,%3};"
        : "+f"(c[0]), "+f"(c[1]), "+f"(c[2]), "+f"(c[3])
        : "r"(a[0]), "r"(a[1]), "r"(a[2]), "r"(a[3]), "r"(b0), "r"(b1));
}

__device__ __forceinline__ void ldsm4(uint32_t* r, uint32_t addr) {
    asm volatile("ldmatrix.sync.aligned.m8n8.x4.shared.b16 {%0,%1,%2,%3}, [%4];"
        : "=r"(r[0]), "=r"(r[1]), "=r"(r[2]), "=r"(r[3]) : "r"(addr));
}

__device__ __forceinline__ uint32_t smem_u32(const void* p) {
    uint32_t a;
    asm("{ .reg .u64 t; cvta.to.shared.u64 t, %1; cvt.u32.u64 %0, t; }" : "=r"(a) : "l"(p));
    return a;
}
#define CP16(dst, src) \
    asm volatile("cp.async.cg.shared.global [%0], [%1], 16;" :: "r"(dst), "l"(src))
#define CP_COMMIT() asm volatile("cp.async.commit_group;" ::: "memory")
#define CP_WAIT1()  asm volatile("cp.async.wait_group 1;" ::: "memory")
#define CP_WAIT0()  asm volatile("cp.async.wait_group 0;" ::: "memory")

__device__ __forceinline__ uint32_t pack_bf(float a, float b) {
    __nv_bfloat162 t;
    t.x = __float2bfloat16(a);
    t.y = __float2bfloat16(b);
    return *(uint32_t*)&t;
}
__device__ __forceinline__ void split_pack(float a, float b, uint32_t& hi, uint32_t& lo) {
    float ah = __bfloat162float(__float2bfloat16(a));
    float bh = __bfloat162float(__float2bfloat16(b));
    hi = pack_bf(ah, bh);
    lo = pack_bf(a - ah, b - bh);
}

// ---------------------------------------------------------------------------
__global__ void split_kernel(const float* __restrict__ in,
                             __nv_bfloat16* __restrict__ hi,
                             __nv_bfloat16* __restrict__ lo, int n) {
    int i = (blockIdx.x * 256 + threadIdx.x) * 4;
    if (i >= n) return;
    float4 v = *(const float4*)(in + i);
    uint32_t h0, l0, h1, l1;
    split_pack(v.x, v.y, h0, l0);
    split_pack(v.z, v.w, h1, l1);
    *(uint32_t*)(hi + i)     = h0;
    *(uint32_t*)(hi + i + 2) = h1;
    *(uint32_t*)(lo + i)     = l0;
    *(uint32_t*)(lo + i + 2) = l1;
}

__global__ void transpose_split(const float* __restrict__ w,
                                __nv_bfloat16* __restrict__ thi,
                                __nv_bfloat16* __restrict__ tlo, int K, int N) {
    __shared__ float st[32][33];
    const int n0 = blockIdx.x * 32, k0 = blockIdx.y * 32;
    const int tx = threadIdx.x, ty = threadIdx.y;          // (32, 8)
    #pragma unroll
    for (int i = 0; i < 4; i++)
        st[ty + 8 * i][tx] = w[(size_t)(k0 + ty + 8 * i) * N + n0 + tx];
    __syncthreads();
    #pragma unroll
    for (int i = 0; i < 4; i++) {
        float f = st[tx][ty + 8 * i];
        __nv_bfloat16 hh = __float2bfloat16(f);
        __nv_bfloat16 ll = __float2bfloat16(f - __bfloat162float(hh));
        size_t o = (size_t)(n0 + ty + 8 * i) * K + k0 + tx;
        thi[o] = hh;
        tlo[o] = ll;
    }
}

// ---------------------------------------------------------------------------
// Tensor-core bf16-split GEMM, 2-stage cp.async + ldmatrix fragment loads.
// ---------------------------------------------------------------------------
#define GRS 40
#define GT_BYTES 10240                 // 128 * 40 * 2
#define GB_OFF   (4 * GT_BYTES)
#define G_SMEM   (8 * GT_BYTES)        // 81920

__global__ __launch_bounds__(256)
void gemm_mma(const __nv_bfloat16* __restrict__ Ahi, const __nv_bfloat16* __restrict__ Alo,
              const __nv_bfloat16* __restrict__ Bhi, const __nv_bfloat16* __restrict__ Blo,
              const float* __restrict__ bias, float* __restrict__ Cmat,
              int N, int K) {
    extern __shared__ __align__(16) char gsm[];
    const uint32_t sb = smem_u32(gsm);

    const int tid = threadIdx.x;
    const int wid = tid >> 5, lane = tid & 31;
    const int g = lane >> 2, tig = lane & 3;
    const int bx = blockIdx.x, by = blockIdx.y;
    const int wm = (wid & 3) * 32;
    const int wn = (wid >> 2) * 64;

    // ldmatrix addressing lanes
    const int aRow = lane & 15, aCol8 = (lane >> 4) * 8;          // A x4
    const int bRow = ((lane >> 4) * 8) + (lane & 7);              // B x4 row-in-pair
    const int bCol8 = ((lane >> 3) & 1) * 8;

    const int lrow = tid >> 2;                  // 0..63 (cp.async row)
    const int lc8  = (tid & 3) * 8;

    float acc[2][8][4];
    #pragma unroll
    for (int mt = 0; mt < 2; mt++)
        #pragma unroll
        for (int nt = 0; nt < 8; nt++)
            #pragma unroll
            for (int j = 0; j < 4; j++) acc[mt][nt][j] = 0.f;

    const int nCh = K >> 5;

    auto load_chunk = [&](int c, int s) {
        const int k0 = c << 5;
        #pragma unroll
        for (int i = 0; i < 2; i++) {
            const int r = lrow + i * 64;
            const size_t ga = (size_t)(by * 128 + r) * K + k0 + lc8;
            const size_t gb = (size_t)(bx * 128 + r) * K + k0 + lc8;
            const uint32_t ro = (uint32_t)(r * (GRS * 2) + lc8 * 2);
            CP16(sb + (s * 2 + 0) * GT_BYTES + ro,          Ahi + ga);
            CP16(sb + (s * 2 + 1) * GT_BYTES + ro,          Alo + ga);
            CP16(sb + GB_OFF + (s * 2 + 0) * GT_BYTES + ro, Bhi + gb);
            CP16(sb + GB_OFF + (s * 2 + 1) * GT_BYTES + ro, Blo + gb);
        }
    };

    load_chunk(0, 0);
    CP_COMMIT();

    for (int c = 0; c < nCh; c++) {
        const int s = c & 1;
        if (c + 1 < nCh) {
            load_chunk(c + 1, s ^ 1);
            CP_COMMIT();
            CP_WAIT1();
        } else {
            CP_WAIT0();
        }
        __syncthreads();

        #pragma unroll
        for (int pass = 0; pass < 3; pass++) {
            const int pa = (pass == 2) ? 1 : 0;
            const int pb = (pass == 1) ? 1 : 0;
            const uint32_t abase = sb + (s * 2 + pa) * GT_BYTES;
            const uint32_t bbase = sb + GB_OFF + (s * 2 + pb) * GT_BYTES;
            #pragma unroll
            for (int ks = 0; ks < 2; ks++) {
                const int kc = ks * 16;
                uint32_t afr[2][4];
                #pragma unroll
                for (int mt = 0; mt < 2; mt++)
                    ldsm4(afr[mt], abase +
                          ((wm + mt * 16 + aRow) * GRS + kc + aCol8) * 2);
                #pragma unroll
                for (int p = 0; p < 4; p++) {
                    uint32_t bfr[4];
                    ldsm4(bfr, bbase +
                          ((wn + p * 16 + bRow) * GRS + kc + bCol8) * 2);
                    mma16816(acc[0][2 * p],     afr[0], bfr[0], bfr[1]);
                    mma16816(acc[1][2 * p],     afr[1], bfr[0], bfr[1]);
                    mma16816(acc[0][2 * p + 1], afr[0], bfr[2], bfr[3]);
                    mma16816(acc[1][2 * p + 1], afr[1], bfr[2], bfr[3]);
                }
            }
        }
        __syncthreads();
    }

    #pragma unroll
    for (int mt = 0; mt < 2; mt++) {
        #pragma unroll
        for (int nt = 0; nt < 8; nt++) {
            const int rg = by * 128 + wm + mt * 16 + g;
            const int cg = bx * 128 + wn + nt * 8 + tig * 2;
            const float bs0 = __ldg(bias + cg), bs1 = __ldg(bias + cg + 1);
            float2 v0, v1;
            v0.x = acc[mt][nt][0] + bs0;
            v0.y = acc[mt][nt][1] + bs1;
            v1.x = acc[mt][nt][2] + bs0;
            v1.y = acc[mt][nt][3] + bs1;
            *(float2*)(Cmat + (size_t)rg * N + cg)       = v0;
            *(float2*)(Cmat + (size_t)(rg + 8) * N + cg) = v1;
        }
    }
}

// ---------------------------------------------------------------------------
// Tensor-core causal flash attention (R4 structure + ldmatrix B-frag loads).
// ---------------------------------------------------------------------------
#define AKS 72               // K/V^T smem row stride (bf16)
#define A_OFF_KSH 0
#define A_OFF_KSL 9216
#define A_OFF_VTH 18432
#define A_OFF_VTL 27648
#define A_OFF_VST 36864      // fp32 staging 64x68
#define A_SMEM    (36864 + 64 * 68 * 4)   // 54272

__global__ __launch_bounds__(256)
void attn_mma(const float* __restrict__ qkv,
              __nv_bfloat16* __restrict__ yhi, __nv_bfloat16* __restrict__ ylo) {
    extern __shared__ char sm[];
    const uint32_t sbase = smem_u32(sm);
    __nv_bfloat16 (*Ksh)[AKS] = (__nv_bfloat16(*)[AKS])(sm + A_OFF_KSH);
    __nv_bfloat16 (*Ksl)[AKS] = (__nv_bfloat16(*)[AKS])(sm + A_OFF_KSL);
    __nv_bfloat16 (*Vth)[AKS] = (__nv_bfloat16(*)[AKS])(sm + A_OFF_VTH);
    __nv_bfloat16 (*Vtl)[AKS] = (__nv_bfloat16(*)[AKS])(sm + A_OFF_VTL);
    float (*Vst)[68]          = (float(*)[68])(sm + A_OFF_VST);

    const int qt = (gridDim.x - 1) - blockIdx.x;   // heavy blocks first
    const int h  = blockIdx.y;
    const int b  = blockIdx.z;
    const int tid = threadIdx.x;
    const int wid = tid >> 5, lane = tid & 31;
    const int g = lane >> 2, tig = lane & 3;

    const int bRow = ((lane >> 4) * 8) + (lane & 7);   // ldmatrix B lanes
    const int bCol8 = ((lane >> 3) & 1) * 8;

    const int qr0 = qt * 128;
    const int row0 = qr0 + wid * 16 + g;
    const float* base = qkv + (size_t)b * Tv * C3v;

    uint32_t qh[4][4], ql[4][4];
    {
        const float sc = 0.125f;
        #pragma unroll
        for (int ks = 0; ks < 4; ks++) {
            const int kc = ks * 16 + tig * 2;
            #pragma unroll
            for (int j = 0; j < 4; j++) {
                const int rr = (j & 1) ? row0 + 8 : row0;
                const int cc = kc + ((j >> 1) ? 8 : 0);
                float2 v = *(const float2*)(base + (size_t)rr * C3v + h * Dv + cc);
                split_pack(v.x * sc, v.y * sc, qh[ks][j], ql[ks][j]);
            }
        }
    }

    float acc_o[8][4];
    #pragma unroll
    for (int nt = 0; nt < 8; nt++)
        #pragma unroll
        for (int j = 0; j < 4; j++) acc_o[nt][j] = 0.f;
    float m0 = -INFINITY, m1 = -INFINITY, l0 = 0.f, l1 = 0.f;

    const int nkv = (qr0 >> 6) + 2;
    for (int kvb = 0; kvb < nkv; kvb++) {
        const int kv0 = kvb * 64;
        #pragma unroll
        for (int i = 0; i < 4; i++) {
            const int u = tid + i * 256;
            const int r = u >> 4, c4 = (u & 15) * 4;
            const float* rowp = base + (size_t)(kv0 + r) * C3v + h * Dv + c4;
            float4 kk = *(const float4*)(rowp + Cv);
            uint32_t h0, lo0, h1, lo1;
            split_pack(kk.x, kk.y, h0, lo0);
            split_pack(kk.z, kk.w, h1, lo1);
            *(uint32_t*)&Ksh[r][c4]     = h0;
            *(uint32_t*)&Ksh[r][c4 + 2] = h1;
            *(uint32_t*)&Ksl[r][c4]     = lo0;
            *(uint32_t*)&Ksl[r][c4 + 2] = lo1;
            *(float4*)&Vst[r][c4] = *(const float4*)(rowp + 2 * Cv);
        }
        __syncthreads();
        {
            const int d = tid >> 2;
            const int kq = (tid & 3) * 16;
            #pragma unroll
            for (int i = 0; i < 16; i++) {
                float f = Vst[kq + i][d];
                __nv_bfloat16 hh = __float2bfloat16(f);
                Vth[d][kq + i] = hh;
                Vtl[d][kq + i] = __float2bfloat16(f - __bfloat162float(hh));
            }
        }
        __syncthreads();

        if (kv0 <= qr0 + wid * 16 + 15) {
            float s_[8][4];
            #pragma unroll
            for (int nt = 0; nt < 8; nt++)
                #pragma unroll
                for (int j = 0; j < 4; j++) s_[nt][j] = 0.f;

            #pragma unroll
            for (int pass = 0; pass < 3; pass++) {
                const uint32_t bbase = sbase +
                    ((pass == 1) ? A_OFF_KSL : A_OFF_KSH);
                #pragma unroll
                for (int ks = 0; ks < 4; ks++) {
                    const uint32_t* A = (pass == 2) ? ql[ks] : qh[ks];
                    const int kc = ks * 16;
                    #pragma unroll
                    for (int p = 0; p < 4; p++) {
                        uint32_t bfr[4];
                        ldsm4(bfr, bbase +
                              ((p * 16 + bRow) * AKS + kc + bCol8) * 2);
                        mma16816(s_[2 * p],     A, bfr[0], bfr[1]);
                        mma16816(s_[2 * p + 1], A, bfr[2], bfr[3]);
                    }
                }
            }

            float rmax0 = -INFINITY, rmax1 = -INFINITY;
            #pragma unroll
            for (int nt = 0; nt < 8; nt++) {
                const int colb = kv0 + nt * 8 + tig * 2;
                #pragma unroll
                for (int j = 0; j < 2; j++) {
                    if (colb + j > row0)     s_[nt][j]     = -INFINITY;
                    if (colb + j > row0 + 8) s_[nt][2 + j] = -INFINITY;
                    rmax0 = fmaxf(rmax0, s_[nt][j]);
                    rmax1 = fmaxf(rmax1, s_[nt][2 + j]);
                }
            }
            rmax0 = fmaxf(rmax0, __shfl_xor_sync(0xffffffff, rmax0, 1));
            rmax0 = fmaxf(rmax0, __shfl_xor_sync(0xffffffff, rmax0, 2));
            rmax1 = fmaxf(rmax1, __shfl_xor_sync(0xffffffff, rmax1, 1));
            rmax1 = fmaxf(rmax1, __shfl_xor_sync(0xffffffff, rmax1, 2));

            const float mn0 = fmaxf(m0, rmax0);
            const float mn1 = fmaxf(m1, rmax1);
            const float cr0 = __expf(m0 - mn0);
            const float cr1 = __expf(m1 - mn1);
            l0 *= cr0; l1 *= cr1;
            #pragma unroll
            for (int nt = 0; nt < 8; nt++) {
                acc_o[nt][0] *= cr0; acc_o[nt][1] *= cr0;
                acc_o[nt][2] *= cr1; acc_o[nt][3] *= cr1;
            }
            m0 = mn0; m1 = mn1;

            uint32_t ph[4][4], pl[4][4];
            float rs0 = 0.f, rs1 = 0.f;
            #pragma unroll
            for (int kt = 0; kt < 4; kt++) {
                float p00, p01, p10, p11;
                p00 = __expf(s_[2 * kt][0] - mn0);
                p01 = __expf(s_[2 * kt][1] - mn0);
                p10 = __expf(s_[2 * kt][2] - mn1);
                p11 = __expf(s_[2 * kt][3] - mn1);
                rs0 += p00 + p01; rs1 += p10 + p11;
                split_pack(p00, p01, ph[kt][0], pl[kt][0]);
                split_pack(p10, p11, ph[kt][1], pl[kt][1]);
                p00 = __expf(s_[2 * kt + 1][0] - mn0);
                p01 = __expf(s_[2 * kt + 1][1] - mn0);
                p10 = __expf(s_[2 * kt + 1][2] - mn1);
                p11 = __expf(s_[2 * kt + 1][3] - mn1);
                rs0 += p00 + p01; rs1 += p10 + p11;
                split_pack(p00, p01, ph[kt][2], pl[kt][2]);
                split_pack(p10, p11, ph[kt][3], pl[kt][3]);
            }
            rs0 += __shfl_xor_sync(0xffffffff, rs0, 1);
            rs0 += __shfl_xor_sync(0xffffffff, rs0, 2);
            rs1 += __shfl_xor_sync(0xffffffff, rs1, 1);
            rs1 += __shfl_xor_sync(0xffffffff, rs1, 2);
            l0 += rs0; l1 += rs1;

            #pragma unroll
            for (int pass = 0; pass < 3; pass++) {
                const uint32_t bbase = sbase +
                    ((pass == 1) ? A_OFF_VTL : A_OFF_VTH);
                #pragma unroll
                for (int kt = 0; kt < 4; kt++) {
                    const uint32_t* A = (pass == 2) ? pl[kt] : ph[kt];
                    const int kc = kt * 16;
                    #pragma unroll
                    for (int p = 0; p < 4; p++) {
                        uint32_t bfr[4];
                        ldsm4(bfr, bbase +
                              ((p * 16 + bRow) * AKS + kc + bCol8) * 2);
                        mma16816(acc_o[2 * p],     A, bfr[0], bfr[1]);
                        mma16816(acc_o[2 * p + 1], A, bfr[2], bfr[3]);
                    }
                }
            }
        }
        __syncthreads();
    }

    const float i0 = 1.f / l0, i1 = 1.f / l1;
    #pragma unroll
    for (int nt = 0; nt < 8; nt++) {
        const int d = nt * 8 + tig * 2;
        const size_t o0 = ((size_t)b * Tv + row0) * Cv + h * Dv + d;
        const size_t o1 = o0 + (size_t)8 * Cv;
        uint32_t hh, lo;
        split_pack(acc_o[nt][0] * i0, acc_o[nt][1] * i0, hh, lo);
        *(uint32_t*)(yhi + o0) = hh;
        *(uint32_t*)(ylo + o0) = lo;
        split_pack(acc_o[nt][2] * i1, acc_o[nt][3] * i1, hh, lo);
        *(uint32_t*)(yhi + o1) = hh;
        *(uint32_t*)(ylo + o1) = lo;
    }
}

// ---------------------------------------------------------------------------
extern "C" void kernel_launch(void* const* d_in, const int* in_sizes, int n_in,
                              void* d_out, int out_size) {
    const float* x      = (const float*)d_in[0];
    const float* w_attn = (const float*)d_in[1];
    const float* b_attn = (const float*)d_in[2];
    const float* w_proj = (const float*)d_in[3];
    const float* b_proj = (const float*)d_in[4];
    float* out = (float*)d_out;

    float* qkv; __nv_bfloat16 *xh, *xl, *wAh, *wAl, *wPh, *wPl, *yh, *yl;
    cudaGetSymbolAddress((void**)&qkv, g_qkv);
    cudaGetSymbolAddress((void**)&xh, g_x_hi);  cudaGetSymbolAddress((void**)&xl, g_x_lo);
    cudaGetSymbolAddress((void**)&wAh, g_wA_hi); cudaGetSymbolAddress((void**)&wAl, g_wA_lo);
    cudaGetSymbolAddress((void**)&wPh, g_wP_hi); cudaGetSymbolAddress((void**)&wPl, g_wP_lo);
    cudaGetSymbolAddress((void**)&yh, g_y_hi);  cudaGetSymbolAddress((void**)&yl, g_y_lo);

    cudaFuncSetAttribute(gemm_mma, cudaFuncAttributeMaxDynamicSharedMemorySize, G_SMEM);
    cudaFuncSetAttribute(attn_mma, cudaFuncAttributeMaxDynamicSharedMemorySize, A_SMEM);

    const int nx = Mv * Cv;
    split_kernel<<<(nx / 4 + 255) / 256, 256>>>(x, xh, xl, nx);
    transpose_split<<<dim3(C3v / 32, Cv / 32), dim3(32, 8)>>>(w_attn, wAh, wAl, Cv, C3v);
    transpose_split<<<dim3(Cv / 32, Cv / 32), dim3(32, 8)>>>(w_proj, wPh, wPl, Cv, Cv);

    gemm_mma<<<dim3(C3v / 128, Mv / 128), 256, G_SMEM>>>(xh, xl, wAh, wAl, b_attn, qkv, C3v, Cv);
    attn_mma<<<dim3(Tv / 128, Hv, Bv), 256, A_SMEM>>>(qkv, yh, yl);
    gemm_mma<<<dim3(Cv / 128, Mv / 128), 256, G_SMEM>>>(yh, yl, wPh, wPl, b_proj, out, Cv, Cv);
}

// round 9
// speedup vs baseline: 1.3096x; 1.0048x over previous
#include <cuda_runtime.h>
#include <cuda_bf16.h>
#include <math.h>
#include <stdint.h>

// Problem constants: B=4, T=2048, C=768, H=12, D=64
#define Bv 4
#define Tv 2048
#define Cv 768
#define Hv 12
#define Dv 64
#define C3v (3 * Cv)     // 2304
#define Mv (Bv * Tv)     // 8192

// ---------------- device scratch (no allocation allowed) -------------------
__device__ float g_qkv[(size_t)Mv * C3v];
__device__ __nv_bfloat16 g_x_hi[(size_t)Mv * Cv];
__device__ __nv_bfloat16 g_x_lo[(size_t)Mv * Cv];
__device__ __nv_bfloat16 g_wA_hi[(size_t)C3v * Cv];
__device__ __nv_bfloat16 g_wA_lo[(size_t)C3v * Cv];
__device__ __nv_bfloat16 g_wP_hi[(size_t)Cv * Cv];
__device__ __nv_bfloat16 g_wP_lo[(size_t)Cv * Cv];
__device__ __nv_bfloat16 g_y_hi[(size_t)Mv * Cv];
__device__ __nv_bfloat16 g_y_lo[(size_t)Mv * Cv];

// ---------------------------------------------------------------------------
__device__ __forceinline__ void mma16816(float* c, const uint32_t* a,
                                         uint32_t b0, uint32_t b1) {
    asm volatile(
        "mma.sync.aligned.m16n8k16.row.col.f32.bf16.bf16.f32 "
        "{%0,%1,%2,%3}, {%4,%5,%6,%7}, {%8,%9}, {%0,%1,%2,%3};"
        : "+f"(c[0]), "+f"(c[1]), "+f"(c[2]), "+f"(c[3])
        : "r"(a[0]), "r"(a[1]), "r"(a[2]), "r"(a[3]), "r"(b0), "r"(b1));
}

__device__ __forceinline__ void ldsm4(uint32_t* r, uint32_t addr) {
    asm volatile("ldmatrix.sync.aligned.m8n8.x4.shared.b16 {%0,%1,%2,%3}, [%4];"
        : "=r"(r[0]), "=r"(r[1]), "=r"(r[2]), "=r"(r[3]) : "r"(addr));
}

__device__ __forceinline__ uint32_t smem_u32(const void* p) {
    uint32_t a;
    asm("{ .reg .u64 t; cvta.to.shared.u64 t, %1; cvt.u32.u64 %0, t; }" : "=r"(a) : "l"(p));
    return a;
}
#define CP16(dst, src) \
    asm volatile("cp.async.cg.shared.global [%0], [%1], 16;" :: "r"(dst), "l"(src))
#define CP_COMMIT() asm volatile("cp.async.commit_group;" ::: "memory")
#define CP_WAIT1()  asm volatile("cp.async.wait_group 1;" ::: "memory")
#define CP_WAIT0()  asm volatile("cp.async.wait_group 0;" ::: "memory")

__device__ __forceinline__ uint32_t pack_bf(float a, float b) {
    __nv_bfloat162 t;
    t.x = __float2bfloat16(a);
    t.y = __float2bfloat16(b);
    return *(uint32_t*)&t;
}
__device__ __forceinline__ void split_pack(float a, float b, uint32_t& hi, uint32_t& lo) {
    float ah = __bfloat162float(__float2bfloat16(a));
    float bh = __bfloat162float(__float2bfloat16(b));
    hi = pack_bf(ah, bh);
    lo = pack_bf(a - ah, b - bh);
}

// ---------------------------------------------------------------------------
__global__ void split_kernel(const float* __restrict__ in,
                             __nv_bfloat16* __restrict__ hi,
                             __nv_bfloat16* __restrict__ lo, int n) {
    int i = (blockIdx.x * 256 + threadIdx.x) * 4;
    if (i >= n) return;
    float4 v = *(const float4*)(in + i);
    uint32_t h0, l0, h1, l1;
    split_pack(v.x, v.y, h0, l0);
    split_pack(v.z, v.w, h1, l1);
    *(uint32_t*)(hi + i)     = h0;
    *(uint32_t*)(hi + i + 2) = h1;
    *(uint32_t*)(lo + i)     = l0;
    *(uint32_t*)(lo + i + 2) = l1;
}

__global__ void transpose_split(const float* __restrict__ w,
                                __nv_bfloat16* __restrict__ thi,
                                __nv_bfloat16* __restrict__ tlo, int K, int N) {
    __shared__ float st[32][33];
    const int n0 = blockIdx.x * 32, k0 = blockIdx.y * 32;
    const int tx = threadIdx.x, ty = threadIdx.y;          // (32, 8)
    #pragma unroll
    for (int i = 0; i < 4; i++)
        st[ty + 8 * i][tx] = w[(size_t)(k0 + ty + 8 * i) * N + n0 + tx];
    __syncthreads();
    #pragma unroll
    for (int i = 0; i < 4; i++) {
        float f = st[tx][ty + 8 * i];
        __nv_bfloat16 hh = __float2bfloat16(f);
        __nv_bfloat16 ll = __float2bfloat16(f - __bfloat162float(hh));
        size_t o = (size_t)(n0 + ty + 8 * i) * K + k0 + tx;
        thi[o] = hh;
        tlo[o] = ll;
    }
}

// ---------------------------------------------------------------------------
// Tensor-core bf16-split GEMM: 128(M) x 64(N) tile, BK=32, 8 warps (4Mx2N),
// warp tile 32x32, 2-stage cp.async, ldmatrix. 2 CTAs/SM via launch_bounds.
// ---------------------------------------------------------------------------
#define GRS 40
#define GTA_BYTES 10240                // A tile: 128 * 40 * 2
#define GTB_BYTES 5120                 // B tile:  64 * 40 * 2
#define GB_OFF    (4 * GTA_BYTES)      // 40960
#define G_SMEM    (GB_OFF + 4 * GTB_BYTES)   // 61440

__global__ __launch_bounds__(256, 2)
void gemm_mma(const __nv_bfloat16* __restrict__ Ahi, const __nv_bfloat16* __restrict__ Alo,
              const __nv_bfloat16* __restrict__ Bhi, const __nv_bfloat16* __restrict__ Blo,
              const float* __restrict__ bias, float* __restrict__ Cmat,
              int N, int K) {
    extern __shared__ __align__(16) char gsm[];
    const uint32_t sb = smem_u32(gsm);

    const int tid = threadIdx.x;
    const int wid = tid >> 5, lane = tid & 31;
    const int g = lane >> 2, tig = lane & 3;
    const int bx = blockIdx.x, by = blockIdx.y;
    const int wm = (wid & 3) * 32;
    const int wn = (wid >> 2) * 32;

    // ldmatrix addressing lanes
    const int aRow = lane & 15, aCol8 = (lane >> 4) * 8;
    const int bRow = ((lane >> 4) * 8) + (lane & 7);
    const int bCol8 = ((lane >> 3) & 1) * 8;

    const int lrow = tid >> 2;                  // 0..63
    const int lc8  = (tid & 3) * 8;

    float acc[2][4][4];
    #pragma unroll
    for (int mt = 0; mt < 2; mt++)
        #pragma unroll
        for (int nt = 0; nt < 4; nt++)
            #pragma unroll
            for (int j = 0; j < 4; j++) acc[mt][nt][j] = 0.f;

    const int nCh = K >> 5;

    auto load_chunk = [&](int c, int s) {
        const int k0 = c << 5;
        #pragma unroll
        for (int i = 0; i < 2; i++) {
            const int r = lrow + i * 64;
            const size_t ga = (size_t)(by * 128 + r) * K + k0 + lc8;
            const uint32_t ro = (uint32_t)(r * (GRS * 2) + lc8 * 2);
            CP16(sb + (s * 2 + 0) * GTA_BYTES + ro, Ahi + ga);
            CP16(sb + (s * 2 + 1) * GTA_BYTES + ro, Alo + ga);
        }
        {
            const size_t gb = (size_t)(bx * 64 + lrow) * K + k0 + lc8;
            const uint32_t ro = (uint32_t)(lrow * (GRS * 2) + lc8 * 2);
            CP16(sb + GB_OFF + (s * 2 + 0) * GTB_BYTES + ro, Bhi + gb);
            CP16(sb + GB_OFF + (s * 2 + 1) * GTB_BYTES + ro, Blo + gb);
        }
    };

    load_chunk(0, 0);
    CP_COMMIT();

    for (int c = 0; c < nCh; c++) {
        const int s = c & 1;
        if (c + 1 < nCh) {
            load_chunk(c + 1, s ^ 1);
            CP_COMMIT();
            CP_WAIT1();
        } else {
            CP_WAIT0();
        }
        __syncthreads();

        #pragma unroll
        for (int pass = 0; pass < 3; pass++) {
            const int pa = (pass == 2) ? 1 : 0;
            const int pb = (pass == 1) ? 1 : 0;
            const uint32_t abase = sb + (s * 2 + pa) * GTA_BYTES;
            const uint32_t bbase = sb + GB_OFF + (s * 2 + pb) * GTB_BYTES;
            #pragma unroll
            for (int ks = 0; ks < 2; ks++) {
                const int kc = ks * 16;
                uint32_t afr[2][4];
                #pragma unroll
                for (int mt = 0; mt < 2; mt++)
                    ldsm4(afr[mt], abase +
                          ((wm + mt * 16 + aRow) * GRS + kc + aCol8) * 2);
                #pragma unroll
                for (int p = 0; p < 2; p++) {
                    uint32_t bfr[4];
                    ldsm4(bfr, bbase +
                          ((wn + p * 16 + bRow) * GRS + kc + bCol8) * 2);
                    mma16816(acc[0][2 * p],     afr[0], bfr[0], bfr[1]);
                    mma16816(acc[1][2 * p],     afr[1], bfr[0], bfr[1]);
                    mma16816(acc[0][2 * p + 1], afr[0], bfr[2], bfr[3]);
                    mma16816(acc[1][2 * p + 1], afr[1], bfr[2], bfr[3]);
                }
            }
        }
        __syncthreads();
    }

    #pragma unroll
    for (int mt = 0; mt < 2; mt++) {
        #pragma unroll
        for (int nt = 0; nt < 4; nt++) {
            const int rg = by * 128 + wm + mt * 16 + g;
            const int cg = bx * 64 + wn + nt * 8 + tig * 2;
            const float bs0 = __ldg(bias + cg), bs1 = __ldg(bias + cg + 1);
            float2 v0, v1;
            v0.x = acc[mt][nt][0] + bs0;
            v0.y = acc[mt][nt][1] + bs1;
            v1.x = acc[mt][nt][2] + bs0;
            v1.y = acc[mt][nt][3] + bs1;
            *(float2*)(Cmat + (size_t)rg * N + cg)       = v0;
            *(float2*)(Cmat + (size_t)(rg + 8) * N + cg) = v1;
        }
    }
}

// ---------------------------------------------------------------------------
// Tensor-core causal flash attention (R7-proven: AKS=72, ldmatrix B-frags).
// 144B row stride is a 16B multiple (ldmatrix alignment) and conflict-free.
// ---------------------------------------------------------------------------
#define AKS 72               // K/V^T smem row stride (bf16)
#define A_OFF_KSH 0
#define A_OFF_KSL 9216
#define A_OFF_VTH 18432
#define A_OFF_VTL 27648
#define A_OFF_VST 36864      // fp32 staging 64x68
#define A_SMEM    (36864 + 64 * 68 * 4)   // 54272

__global__ __launch_bounds__(256)
void attn_mma(const float* __restrict__ qkv,
              __nv_bfloat16* __restrict__ yhi, __nv_bfloat16* __restrict__ ylo) {
    extern __shared__ char sm[];
    const uint32_t sbase = smem_u32(sm);
    __nv_bfloat16 (*Ksh)[AKS] = (__nv_bfloat16(*)[AKS])(sm + A_OFF_KSH);
    __nv_bfloat16 (*Ksl)[AKS] = (__nv_bfloat16(*)[AKS])(sm + A_OFF_KSL);
    __nv_bfloat16 (*Vth)[AKS] = (__nv_bfloat16(*)[AKS])(sm + A_OFF_VTH);
    __nv_bfloat16 (*Vtl)[AKS] = (__nv_bfloat16(*)[AKS])(sm + A_OFF_VTL);
    float (*Vst)[68]          = (float(*)[68])(sm + A_OFF_VST);

    const int qt = (gridDim.x - 1) - blockIdx.x;   // heavy blocks first
    const int h  = blockIdx.y;
    const int b  = blockIdx.z;
    const int tid = threadIdx.x;
    const int wid = tid >> 5, lane = tid & 31;
    const int g = lane >> 2, tig = lane & 3;

    const int bRow = ((lane >> 4) * 8) + (lane & 7);   // ldmatrix B lanes
    const int bCol8 = ((lane >> 3) & 1) * 8;

    const int qr0 = qt * 128;
    const int row0 = qr0 + wid * 16 + g;
    const float* base = qkv + (size_t)b * Tv * C3v;

    uint32_t qh[4][4], ql[4][4];
    {
        const float sc = 0.125f;
        #pragma unroll
        for (int ks = 0; ks < 4; ks++) {
            const int kc = ks * 16 + tig * 2;
            #pragma unroll
            for (int j = 0; j < 4; j++) {
                const int rr = (j & 1) ? row0 + 8 : row0;
                const int cc = kc + ((j >> 1) ? 8 : 0);
                float2 v = *(const float2*)(base + (size_t)rr * C3v + h * Dv + cc);
                split_pack(v.x * sc, v.y * sc, qh[ks][j], ql[ks][j]);
            }
        }
    }

    float acc_o[8][4];
    #pragma unroll
    for (int nt = 0; nt < 8; nt++)
        #pragma unroll
        for (int j = 0; j < 4; j++) acc_o[nt][j] = 0.f;
    float m0 = -INFINITY, m1 = -INFINITY, l0 = 0.f, l1 = 0.f;

    const int nkv = (qr0 >> 6) + 2;
    for (int kvb = 0; kvb < nkv; kvb++) {
        const int kv0 = kvb * 64;
        #pragma unroll
        for (int i = 0; i < 4; i++) {
            const int u = tid + i * 256;
            const int r = u >> 4, c4 = (u & 15) * 4;
            const float* rowp = base + (size_t)(kv0 + r) * C3v + h * Dv + c4;
            float4 kk = *(const float4*)(rowp + Cv);
            uint32_t h0, lo0, h1, lo1;
            split_pack(kk.x, kk.y, h0, lo0);
            split_pack(kk.z, kk.w, h1, lo1);
            *(uint32_t*)&Ksh[r][c4]     = h0;
            *(uint32_t*)&Ksh[r][c4 + 2] = h1;
            *(uint32_t*)&Ksl[r][c4]     = lo0;
            *(uint32_t*)&Ksl[r][c4 + 2] = lo1;
            *(float4*)&Vst[r][c4] = *(const float4*)(rowp + 2 * Cv);
        }
        __syncthreads();
        {
            const int d = tid >> 2;
            const int kq = (tid & 3) * 16;
            #pragma unroll
            for (int i = 0; i < 16; i++) {
                float f = Vst[kq + i][d];
                __nv_bfloat16 hh = __float2bfloat16(f);
                Vth[d][kq + i] = hh;
                Vtl[d][kq + i] = __float2bfloat16(f - __bfloat162float(hh));
            }
        }
        __syncthreads();

        if (kv0 <= qr0 + wid * 16 + 15) {
            float s_[8][4];
            #pragma unroll
            for (int nt = 0; nt < 8; nt++)
                #pragma unroll
                for (int j = 0; j < 4; j++) s_[nt][j] = 0.f;

            #pragma unroll
            for (int pass = 0; pass < 3; pass++) {
                const uint32_t bbase = sbase +
                    ((pass == 1) ? A_OFF_KSL : A_OFF_KSH);
                #pragma unroll
                for (int ks = 0; ks < 4; ks++) {
                    const uint32_t* A = (pass == 2) ? ql[ks] : qh[ks];
                    const int kc = ks * 16;
                    #pragma unroll
                    for (int p = 0; p < 4; p++) {
                        uint32_t bfr[4];
                        ldsm4(bfr, bbase +
                              ((p * 16 + bRow) * AKS + kc + bCol8) * 2);
                        mma16816(s_[2 * p],     A, bfr[0], bfr[1]);
                        mma16816(s_[2 * p + 1], A, bfr[2], bfr[3]);
                    }
                }
            }

            float rmax0 = -INFINITY, rmax1 = -INFINITY;
            #pragma unroll
            for (int nt = 0; nt < 8; nt++) {
                const int colb = kv0 + nt * 8 + tig * 2;
                #pragma unroll
                for (int j = 0; j < 2; j++) {
                    if (colb + j > row0)     s_[nt][j]     = -INFINITY;
                    if (colb + j > row0 + 8) s_[nt][2 + j] = -INFINITY;
                    rmax0 = fmaxf(rmax0, s_[nt][j]);
                    rmax1 = fmaxf(rmax1, s_[nt][2 + j]);
                }
            }
            rmax0 = fmaxf(rmax0, __shfl_xor_sync(0xffffffff, rmax0, 1));
            rmax0 = fmaxf(rmax0, __shfl_xor_sync(0xffffffff, rmax0, 2));
            rmax1 = fmaxf(rmax1, __shfl_xor_sync(0xffffffff, rmax1, 1));
            rmax1 = fmaxf(rmax1, __shfl_xor_sync(0xffffffff, rmax1, 2));

            const float mn0 = fmaxf(m0, rmax0);
            const float mn1 = fmaxf(m1, rmax1);
            const float cr0 = __expf(m0 - mn0);
            const float cr1 = __expf(m1 - mn1);
            l0 *= cr0; l1 *= cr1;
            #pragma unroll
            for (int nt = 0; nt < 8; nt++) {
                acc_o[nt][0] *= cr0; acc_o[nt][1] *= cr0;
                acc_o[nt][2] *= cr1; acc_o[nt][3] *= cr1;
            }
            m0 = mn0; m1 = mn1;

            uint32_t ph[4][4], pl[4][4];
            float rs0 = 0.f, rs1 = 0.f;
            #pragma unroll
            for (int kt = 0; kt < 4; kt++) {
                float p00, p01, p10, p11;
                p00 = __expf(s_[2 * kt][0] - mn0);
                p01 = __expf(s_[2 * kt][1] - mn0);
                p10 = __expf(s_[2 * kt][2] - mn1);
                p11 = __expf(s_[2 * kt][3] - mn1);
                rs0 += p00 + p01; rs1 += p10 + p11;
                split_pack(p00, p01, ph[kt][0], pl[kt][0]);
                split_pack(p10, p11, ph[kt][1], pl[kt][1]);
                p00 = __expf(s_[2 * kt + 1][0] - mn0);
                p01 = __expf(s_[2 * kt + 1][1] - mn0);
                p10 = __expf(s_[2 * kt + 1][2] - mn1);
                p11 = __expf(s_[2 * kt + 1][3] - mn1);
                rs0 += p00 + p01; rs1 += p10 + p11;
                split_pack(p00, p01, ph[kt][2], pl[kt][2]);
                split_pack(p10, p11, ph[kt][3], pl[kt][3]);
            }
            rs0 += __shfl_xor_sync(0xffffffff, rs0, 1);
            rs0 += __shfl_xor_sync(0xffffffff, rs0, 2);
            rs1 += __shfl_xor_sync(0xffffffff, rs1, 1);
            rs1 += __shfl_xor_sync(0xffffffff, rs1, 2);
            l0 += rs0; l1 += rs1;

            #pragma unroll
            for (int pass = 0; pass < 3; pass++) {
                const uint32_t bbase = sbase +
                    ((pass == 1) ? A_OFF_VTL : A_OFF_VTH);
                #pragma unroll
                for (int kt = 0; kt < 4; kt++) {
                    const uint32_t* A = (pass == 2) ? pl[kt] : ph[kt];
                    const int kc = kt * 16;
                    #pragma unroll
                    for (int p = 0; p < 4; p++) {
                        uint32_t bfr[4];
                        ldsm4(bfr, bbase +
                              ((p * 16 + bRow) * AKS + kc + bCol8) * 2);
                        mma16816(acc_o[2 * p],     A, bfr[0], bfr[1]);
                        mma16816(acc_o[2 * p + 1], A, bfr[2], bfr[3]);
                    }
                }
            }
        }
        __syncthreads();
    }

    const float i0 = 1.f / l0, i1 = 1.f / l1;
    #pragma unroll
    for (int nt = 0; nt < 8; nt++) {
        const int d = nt * 8 + tig * 2;
        const size_t o0 = ((size_t)b * Tv + row0) * Cv + h * Dv + d;
        const size_t o1 = o0 + (size_t)8 * Cv;
        uint32_t hh, lo;
        split_pack(acc_o[nt][0] * i0, acc_o[nt][1] * i0, hh, lo);
        *(uint32_t*)(yhi + o0) = hh;
        *(uint32_t*)(ylo + o0) = lo;
        split_pack(acc_o[nt][2] * i1, acc_o[nt][3] * i1, hh, lo);
        *(uint32_t*)(yhi + o1) = hh;
        *(uint32_t*)(ylo + o1) = lo;
    }
}

// ---------------------------------------------------------------------------
extern "C" void kernel_launch(void* const* d_in, const int* in_sizes, int n_in,
                              void* d_out, int out_size) {
    const float* x      = (const float*)d_in[0];
    const float* w_attn = (const float*)d_in[1];
    const float* b_attn = (const float*)d_in[2];
    const float* w_proj = (const float*)d_in[3];
    const float* b_proj = (const float*)d_in[4];
    float* out = (float*)d_out;

    float* qkv; __nv_bfloat16 *xh, *xl, *wAh, *wAl, *wPh, *wPl, *yh, *yl;
    cudaGetSymbolAddress((void**)&qkv, g_qkv);
    cudaGetSymbolAddress((void**)&xh, g_x_hi);  cudaGetSymbolAddress((void**)&xl, g_x_lo);
    cudaGetSymbolAddress((void**)&wAh, g_wA_hi); cudaGetSymbolAddress((void**)&wAl, g_wA_lo);
    cudaGetSymbolAddress((void**)&wPh, g_wP_hi); cudaGetSymbolAddress((void**)&wPl, g_wP_lo);
    cudaGetSymbolAddress((void**)&yh, g_y_hi);  cudaGetSymbolAddress((void**)&yl, g_y_lo);

    cudaFuncSetAttribute(gemm_mma, cudaFuncAttributeMaxDynamicSharedMemorySize, G_SMEM);
    cudaFuncSetAttribute(attn_mma, cudaFuncAttributeMaxDynamicSharedMemorySize, A_SMEM);

    const int nx = Mv * Cv;
    split_kernel<<<(nx / 4 + 255) / 256, 256>>>(x, xh, xl, nx);
    transpose_split<<<dim3(C3v / 32, Cv / 32), dim3(32, 8)>>>(w_attn, wAh, wAl, Cv, C3v);
    transpose_split<<<dim3(Cv / 32, Cv / 32), dim3(32, 8)>>>(w_proj, wPh, wPl, Cv, Cv);

    gemm_mma<<<dim3(C3v / 64, Mv / 128), 256, G_SMEM>>>(xh, xl, wAh, wAl, b_attn, qkv, C3v, Cv);
    attn_mma<<<dim3(Tv / 128, Hv, Bv), 256, A_SMEM>>>(qkv, yh, yl);
    gemm_mma<<<dim3(Cv / 64, Mv / 128), 256, G_SMEM>>>(yh, yl, wPh, wPl, b_proj, out, Cv, Cv);
}

// round 10
// speedup vs baseline: 1.6781x; 1.2814x over previous
#include <cuda_runtime.h>
#include <cuda_fp16.h>
#include <math.h>
#include <stdint.h>

// Problem constants: B=4, T=2048, C=768, H=12, D=64
#define Bv 4
#define Tv 2048
#define Cv 768
#define Hv 12
#define Dv 64
#define C3v (3 * Cv)     // 2304
#define Mv (Bv * Tv)     // 8192

// ---------------- device scratch (no allocation allowed) -------------------
__device__ float g_qkv[(size_t)Mv * C3v];
__device__ __half g_x_hi[(size_t)Mv * Cv];
__device__ __half g_x_lo[(size_t)Mv * Cv];
__device__ __half g_wA[(size_t)C3v * Cv];     // transposed [3C, C], single fp16
__device__ __half g_wP[(size_t)Cv * Cv];      // transposed [C, C], single fp16
__device__ __half g_y_hi[(size_t)Mv * Cv];
__device__ __half g_y_lo[(size_t)Mv * Cv];

// ---------------------------------------------------------------------------
__device__ __forceinline__ void mma16816(float* c, const uint32_t* a,
                                         uint32_t b0, uint32_t b1) {
    asm volatile(
        "mma.sync.aligned.m16n8k16.row.col.f32.f16.f16.f32 "
        "{%0,%1,%2,%3}, {%4,%5,%6,%7}, {%8,%9}, {%0,%1,%2,%3};"
        : "+f"(c[0]), "+f"(c[1]), "+f"(c[2]), "+f"(c[3])
        : "r"(a[0]), "r"(a[1]), "r"(a[2]), "r"(a[3]), "r"(b0), "r"(b1));
}

__device__ __forceinline__ void ldsm4(uint32_t* r, uint32_t addr) {
    asm volatile("ldmatrix.sync.aligned.m8n8.x4.shared.b16 {%0,%1,%2,%3}, [%4];"
        : "=r"(r[0]), "=r"(r[1]), "=r"(r[2]), "=r"(r[3]) : "r"(addr));
}

__device__ __forceinline__ uint32_t smem_u32(const void* p) {
    uint32_t a;
    asm("{ .reg .u64 t; cvta.to.shared.u64 t, %1; cvt.u32.u64 %0, t; }" : "=r"(a) : "l"(p));
    return a;
}
#define CP16(dst, src) \
    asm volatile("cp.async.cg.shared.global [%0], [%1], 16;" :: "r"(dst), "l"(src))
#define CP_COMMIT() asm volatile("cp.async.commit_group;" ::: "memory")
#define CP_WAIT1()  asm volatile("cp.async.wait_group 1;" ::: "memory")
#define CP_WAIT0()  asm volatile("cp.async.wait_group 0;" ::: "memory")

__device__ __forceinline__ uint32_t pack_h(float a, float b) {
    __half2 t;
    t.x = __float2half_rn(a);
    t.y = __float2half_rn(b);
    return *(uint32_t*)&t;
}
// split pair into fp16 hi pack + residual-lo pack (hi+lo ~exactly represents input)
__device__ __forceinline__ void split_pack_h(float a, float b, uint32_t& hi, uint32_t& lo) {
    __half ah = __float2half_rn(a);
    __half bh = __float2half_rn(b);
    __half2 t; t.x = ah; t.y = bh;
    hi = *(uint32_t*)&t;
    lo = pack_h(a - __half2float(ah), b - __half2float(bh));
}

// ---------------------------------------------------------------------------
// split fp32 x -> (hi, lo) fp16
// ---------------------------------------------------------------------------
__global__ void split_kernel(const float* __restrict__ in,
                             __half* __restrict__ hi,
                             __half* __restrict__ lo, int n) {
    int i = (blockIdx.x * 256 + threadIdx.x) * 4;
    if (i >= n) return;
    float4 v = *(const float4*)(in + i);
    uint32_t h0, l0, h1, l1;
    split_pack_h(v.x, v.y, h0, l0);
    split_pack_h(v.z, v.w, h1, l1);
    *(uint32_t*)(hi + i)     = h0;
    *(uint32_t*)(hi + i + 2) = h1;
    *(uint32_t*)(lo + i)     = l0;
    *(uint32_t*)(lo + i + 2) = l1;
}

// transpose + cvt: w[K,N] fp32 -> wT[N,K] fp16 (single precision level)
__global__ void transpose_cvt(const float* __restrict__ w,
                              __half* __restrict__ t_, int K, int N) {
    __shared__ float st[32][33];
    const int n0 = blockIdx.x * 32, k0 = blockIdx.y * 32;
    const int tx = threadIdx.x, ty = threadIdx.y;          // (32, 8)
    #pragma unroll
    for (int i = 0; i < 4; i++)
        st[ty + 8 * i][tx] = w[(size_t)(k0 + ty + 8 * i) * N + n0 + tx];
    __syncthreads();
    #pragma unroll
    for (int i = 0; i < 4; i++)
        t_[(size_t)(n0 + ty + 8 * i) * K + k0 + tx] =
            __float2half_rn(st[tx][ty + 8 * i]);
}

// ---------------------------------------------------------------------------
// fp16 2-pass GEMM: C[M,N] = (Ahi+Alo)[M,K] @ B[N,K]^T + bias
// 128x64 tile, BK=32, 8 warps, 2-stage cp.async, ldmatrix, 2 CTAs/SM.
// ---------------------------------------------------------------------------
#define GRS 40
#define GTA_BYTES 10240                // A tile: 128 * 40 * 2
#define GTB_BYTES 5120                 // B tile:  64 * 40 * 2
#define GB_OFF    (4 * GTA_BYTES)      // 40960
#define G_SMEM    (GB_OFF + 2 * GTB_BYTES)   // 51200

__global__ __launch_bounds__(256, 2)
void gemm_mma(const __half* __restrict__ Ahi, const __half* __restrict__ Alo,
              const __half* __restrict__ Bm,
              const float* __restrict__ bias, float* __restrict__ Cmat,
              int N, int K) {
    extern __shared__ __align__(16) char gsm[];
    const uint32_t sb = smem_u32(gsm);

    const int tid = threadIdx.x;
    const int wid = tid >> 5, lane = tid & 31;
    const int g = lane >> 2, tig = lane & 3;
    const int bx = blockIdx.x, by = blockIdx.y;
    const int wm = (wid & 3) * 32;
    const int wn = (wid >> 2) * 32;

    const int aRow = lane & 15, aCol8 = (lane >> 4) * 8;
    const int bRow = ((lane >> 4) * 8) + (lane & 7);
    const int bCol8 = ((lane >> 3) & 1) * 8;

    const int lrow = tid >> 2;                  // 0..63
    const int lc8  = (tid & 3) * 8;

    float acc[2][4][4];
    #pragma unroll
    for (int mt = 0; mt < 2; mt++)
        #pragma unroll
        for (int nt = 0; nt < 4; nt++)
            #pragma unroll
            for (int j = 0; j < 4; j++) acc[mt][nt][j] = 0.f;

    const int nCh = K >> 5;

    auto load_chunk = [&](int c, int s) {
        const int k0 = c << 5;
        #pragma unroll
        for (int i = 0; i < 2; i++) {
            const int r = lrow + i * 64;
            const size_t ga = (size_t)(by * 128 + r) * K + k0 + lc8;
            const uint32_t ro = (uint32_t)(r * (GRS * 2) + lc8 * 2);
            CP16(sb + (s * 2 + 0) * GTA_BYTES + ro, Ahi + ga);
            CP16(sb + (s * 2 + 1) * GTA_BYTES + ro, Alo + ga);
        }
        {
            const size_t gb = (size_t)(bx * 64 + lrow) * K + k0 + lc8;
            const uint32_t ro = (uint32_t)(lrow * (GRS * 2) + lc8 * 2);
            CP16(sb + GB_OFF + s * GTB_BYTES + ro, Bm + gb);
        }
    };

    load_chunk(0, 0);
    CP_COMMIT();

    for (int c = 0; c < nCh; c++) {
        const int s = c & 1;
        if (c + 1 < nCh) {
            load_chunk(c + 1, s ^ 1);
            CP_COMMIT();
            CP_WAIT1();
        } else {
            CP_WAIT0();
        }
        __syncthreads();

        #pragma unroll
        for (int pass = 0; pass < 2; pass++) {
            const uint32_t abase = sb + (s * 2 + pass) * GTA_BYTES;
            const uint32_t bbase = sb + GB_OFF + s * GTB_BYTES;
            #pragma unroll
            for (int ks = 0; ks < 2; ks++) {
                const int kc = ks * 16;
                uint32_t afr[2][4];
                #pragma unroll
                for (int mt = 0; mt < 2; mt++)
                    ldsm4(afr[mt], abase +
                          ((wm + mt * 16 + aRow) * GRS + kc + aCol8) * 2);
                #pragma unroll
                for (int p = 0; p < 2; p++) {
                    uint32_t bfr[4];
                    ldsm4(bfr, bbase +
                          ((wn + p * 16 + bRow) * GRS + kc + bCol8) * 2);
                    mma16816(acc[0][2 * p],     afr[0], bfr[0], bfr[1]);
                    mma16816(acc[1][2 * p],     afr[1], bfr[0], bfr[1]);
                    mma16816(acc[0][2 * p + 1], afr[0], bfr[2], bfr[3]);
                    mma16816(acc[1][2 * p + 1], afr[1], bfr[2], bfr[3]);
                }
            }
        }
        __syncthreads();
    }

    #pragma unroll
    for (int mt = 0; mt < 2; mt++) {
        #pragma unroll
        for (int nt = 0; nt < 4; nt++) {
            const int rg = by * 128 + wm + mt * 16 + g;
            const int cg = bx * 64 + wn + nt * 8 + tig * 2;
            const float bs0 = __ldg(bias + cg), bs1 = __ldg(bias + cg + 1);
            float2 v0, v1;
            v0.x = acc[mt][nt][0] + bs0;
            v0.y = acc[mt][nt][1] + bs1;
            v1.x = acc[mt][nt][2] + bs0;
            v1.y = acc[mt][nt][3] + bs1;
            *(float2*)(Cmat + (size_t)rg * N + cg)       = v0;
            *(float2*)(Cmat + (size_t)(rg + 8) * N + cg) = v1;
        }
    }
}

// ---------------------------------------------------------------------------
// fp16 2-pass causal flash attention (R9 structure; K and V single fp16,
// Q and P split hi/lo).
// ---------------------------------------------------------------------------
#define AKS 72               // K/V^T smem row stride (fp16)
#define A_OFF_KSH 0
#define A_OFF_VTH 9216
#define A_OFF_VST 18432      // fp32 staging 64x68
#define A_SMEM    (18432 + 64 * 68 * 4)   // 35840

__global__ __launch_bounds__(256)
void attn_mma(const float* __restrict__ qkv,
              __half* __restrict__ yhi, __half* __restrict__ ylo) {
    extern __shared__ char sm[];
    const uint32_t sbase = smem_u32(sm);
    __half (*Ksh)[AKS] = (__half(*)[AKS])(sm + A_OFF_KSH);
    __half (*Vth)[AKS] = (__half(*)[AKS])(sm + A_OFF_VTH);
    float (*Vst)[68]   = (float(*)[68])(sm + A_OFF_VST);

    const int qt = (gridDim.x - 1) - blockIdx.x;   // heavy blocks first
    const int h  = blockIdx.y;
    const int b  = blockIdx.z;
    const int tid = threadIdx.x;
    const int wid = tid >> 5, lane = tid & 31;
    const int g = lane >> 2, tig = lane & 3;

    const int bRow = ((lane >> 4) * 8) + (lane & 7);
    const int bCol8 = ((lane >> 3) & 1) * 8;

    const int qr0 = qt * 128;
    const int row0 = qr0 + wid * 16 + g;
    const float* base = qkv + (size_t)b * Tv * C3v;

    uint32_t qh[4][4], ql[4][4];
    {
        const float sc = 0.125f;
        #pragma unroll
        for (int ks = 0; ks < 4; ks++) {
            const int kc = ks * 16 + tig * 2;
            #pragma unroll
            for (int j = 0; j < 4; j++) {
                const int rr = (j & 1) ? row0 + 8 : row0;
                const int cc = kc + ((j >> 1) ? 8 : 0);
                float2 v = *(const float2*)(base + (size_t)rr * C3v + h * Dv + cc);
                split_pack_h(v.x * sc, v.y * sc, qh[ks][j], ql[ks][j]);
            }
        }
    }

    float acc_o[8][4];
    #pragma unroll
    for (int nt = 0; nt < 8; nt++)
        #pragma unroll
        for (int j = 0; j < 4; j++) acc_o[nt][j] = 0.f;
    float m0 = -INFINITY, m1 = -INFINITY, l0 = 0.f, l1 = 0.f;

    const int nkv = (qr0 >> 6) + 2;
    for (int kvb = 0; kvb < nkv; kvb++) {
        const int kv0 = kvb * 64;
        #pragma unroll
        for (int i = 0; i < 4; i++) {
            const int u = tid + i * 256;
            const int r = u >> 4, c4 = (u & 15) * 4;
            const float* rowp = base + (size_t)(kv0 + r) * C3v + h * Dv + c4;
            float4 kk = *(const float4*)(rowp + Cv);
            *(uint32_t*)&Ksh[r][c4]     = pack_h(kk.x, kk.y);
            *(uint32_t*)&Ksh[r][c4 + 2] = pack_h(kk.z, kk.w);
            *(float4*)&Vst[r][c4] = *(const float4*)(rowp + 2 * Cv);
        }
        __syncthreads();
        {
            const int d = tid >> 2;
            const int kq = (tid & 3) * 16;
            #pragma unroll
            for (int i = 0; i < 16; i += 2)
                *(uint32_t*)&Vth[d][kq + i] =
                    pack_h(Vst[kq + i][d], Vst[kq + i + 1][d]);
        }
        __syncthreads();

        if (kv0 <= qr0 + wid * 16 + 15) {
            float s_[8][4];
            #pragma unroll
            for (int nt = 0; nt < 8; nt++)
                #pragma unroll
                for (int j = 0; j < 4; j++) s_[nt][j] = 0.f;

            #pragma unroll
            for (int pass = 0; pass < 2; pass++) {
                const uint32_t bbase = sbase + A_OFF_KSH;
                #pragma unroll
                for (int ks = 0; ks < 4; ks++) {
                    const uint32_t* A = pass ? ql[ks] : qh[ks];
                    const int kc = ks * 16;
                    #pragma unroll
                    for (int p = 0; p < 4; p++) {
                        uint32_t bfr[4];
                        ldsm4(bfr, bbase +
                              ((p * 16 + bRow) * AKS + kc + bCol8) * 2);
                        mma16816(s_[2 * p],     A, bfr[0], bfr[1]);
                        mma16816(s_[2 * p + 1], A, bfr[2], bfr[3]);
                    }
                }
            }

            float rmax0 = -INFINITY, rmax1 = -INFINITY;
            #pragma unroll
            for (int nt = 0; nt < 8; nt++) {
                const int colb = kv0 + nt * 8 + tig * 2;
                #pragma unroll
                for (int j = 0; j < 2; j++) {
                    if (colb + j > row0)     s_[nt][j]     = -INFINITY;
                    if (colb + j > row0 + 8) s_[nt][2 + j] = -INFINITY;
                    rmax0 = fmaxf(rmax0, s_[nt][j]);
                    rmax1 = fmaxf(rmax1, s_[nt][2 + j]);
                }
            }
            rmax0 = fmaxf(rmax0, __shfl_xor_sync(0xffffffff, rmax0, 1));
            rmax0 = fmaxf(rmax0, __shfl_xor_sync(0xffffffff, rmax0, 2));
            rmax1 = fmaxf(rmax1, __shfl_xor_sync(0xffffffff, rmax1, 1));
            rmax1 = fmaxf(rmax1, __shfl_xor_sync(0xffffffff, rmax1, 2));

            const float mn0 = fmaxf(m0, rmax0);
            const float mn1 = fmaxf(m1, rmax1);
            const float cr0 = __expf(m0 - mn0);
            const float cr1 = __expf(m1 - mn1);
            l0 *= cr0; l1 *= cr1;
            #pragma unroll
            for (int nt = 0; nt < 8; nt++) {
                acc_o[nt][0] *= cr0; acc_o[nt][1] *= cr0;
                acc_o[nt][2] *= cr1; acc_o[nt][3] *= cr1;
            }
            m0 = mn0; m1 = mn1;

            uint32_t ph[4][4], pl[4][4];
            float rs0 = 0.f, rs1 = 0.f;
            #pragma unroll
            for (int kt = 0; kt < 4; kt++) {
                float p00, p01, p10, p11;
                p00 = __expf(s_[2 * kt][0] - mn0);
                p01 = __expf(s_[2 * kt][1] - mn0);
                p10 = __expf(s_[2 * kt][2] - mn1);
                p11 = __expf(s_[2 * kt][3] - mn1);
                rs0 += p00 + p01; rs1 += p10 + p11;
                split_pack_h(p00, p01, ph[kt][0], pl[kt][0]);
                split_pack_h(p10, p11, ph[kt][1], pl[kt][1]);
                p00 = __expf(s_[2 * kt + 1][0] - mn0);
                p01 = __expf(s_[2 * kt + 1][1] - mn0);
                p10 = __expf(s_[2 * kt + 1][2] - mn1);
                p11 = __expf(s_[2 * kt + 1][3] - mn1);
                rs0 += p00 + p01; rs1 += p10 + p11;
                split_pack_h(p00, p01, ph[kt][2], pl[kt][2]);
                split_pack_h(p10, p11, ph[kt][3], pl[kt][3]);
            }
            rs0 += __shfl_xor_sync(0xffffffff, rs0, 1);
            rs0 += __shfl_xor_sync(0xffffffff, rs0, 2);
            rs1 += __shfl_xor_sync(0xffffffff, rs1, 1);
            rs1 += __shfl_xor_sync(0xffffffff, rs1, 2);
            l0 += rs0; l1 += rs1;

            #pragma unroll
            for (int pass = 0; pass < 2; pass++) {
                const uint32_t bbase = sbase + A_OFF_VTH;
                #pragma unroll
                for (int kt = 0; kt < 4; kt++) {
                    const uint32_t* A = pass ? pl[kt] : ph[kt];
                    const int kc = kt * 16;
                    #pragma unroll
                    for (int p = 0; p < 4; p++) {
                        uint32_t bfr[4];
                        ldsm4(bfr, bbase +
                              ((p * 16 + bRow) * AKS + kc + bCol8) * 2);
                        mma16816(acc_o[2 * p],     A, bfr[0], bfr[1]);
                        mma16816(acc_o[2 * p + 1], A, bfr[2], bfr[3]);
                    }
                }
            }
        }
        __syncthreads();
    }

    const float i0 = 1.f / l0, i1 = 1.f / l1;
    #pragma unroll
    for (int nt = 0; nt < 8; nt++) {
        const int d = nt * 8 + tig * 2;
        const size_t o0 = ((size_t)b * Tv + row0) * Cv + h * Dv + d;
        const size_t o1 = o0 + (size_t)8 * Cv;
        uint32_t hh, lo;
        split_pack_h(acc_o[nt][0] * i0, acc_o[nt][1] * i0, hh, lo);
        *(uint32_t*)(yhi + o0) = hh;
        *(uint32_t*)(ylo + o0) = lo;
        split_pack_h(acc_o[nt][2] * i1, acc_o[nt][3] * i1, hh, lo);
        *(uint32_t*)(yhi + o1) = hh;
        *(uint32_t*)(ylo + o1) = lo;
    }
}

// ---------------------------------------------------------------------------
extern "C" void kernel_launch(void* const* d_in, const int* in_sizes, int n_in,
                              void* d_out, int out_size) {
    const float* x      = (const float*)d_in[0];
    const float* w_attn = (const float*)d_in[1];
    const float* b_attn = (const float*)d_in[2];
    const float* w_proj = (const float*)d_in[3];
    const float* b_proj = (const float*)d_in[4];
    float* out = (float*)d_out;

    float* qkv; __half *xh, *xl, *wA, *wP, *yh, *yl;
    cudaGetSymbolAddress((void**)&qkv, g_qkv);
    cudaGetSymbolAddress((void**)&xh, g_x_hi);
    cudaGetSymbolAddress((void**)&xl, g_x_lo);
    cudaGetSymbolAddress((void**)&wA, g_wA);
    cudaGetSymbolAddress((void**)&wP, g_wP);
    cudaGetSymbolAddress((void**)&yh, g_y_hi);
    cudaGetSymbolAddress((void**)&yl, g_y_lo);

    cudaFuncSetAttribute(gemm_mma, cudaFuncAttributeMaxDynamicSharedMemorySize, G_SMEM);
    cudaFuncSetAttribute(attn_mma, cudaFuncAttributeMaxDynamicSharedMemorySize, A_SMEM);

    const int nx = Mv * Cv;
    split_kernel<<<(nx / 4 + 255) / 256, 256>>>(x, xh, xl, nx);
    transpose_cvt<<<dim3(C3v / 32, Cv / 32), dim3(32, 8)>>>(w_attn, wA, Cv, C3v);
    transpose_cvt<<<dim3(Cv / 32, Cv / 32), dim3(32, 8)>>>(w_proj, wP, Cv, Cv);

    gemm_mma<<<dim3(C3v / 64, Mv / 128), 256, G_SMEM>>>(xh, xl, wA, b_attn, qkv, C3v, Cv);
    attn_mma<<<dim3(Tv / 128, Hv, Bv), 256, A_SMEM>>>(qkv, yh, yl);
    gemm_mma<<<dim3(Cv / 64, Mv / 128), 256, G_SMEM>>>(yh, yl, wP, b_proj, out, Cv, Cv);
}

// round 11
// speedup vs baseline: 2.4666x; 1.4699x over previous
#include <cuda_runtime.h>
#include <cuda_fp16.h>
#include <math.h>
#include <stdint.h>

// Problem constants: B=4, T=2048, C=768, H=12, D=64
#define Bv 4
#define Tv 2048
#define Cv 768
#define Hv 12
#define Dv 64
#define C3v (3 * Cv)     // 2304
#define Mv (Bv * Tv)     // 8192

// ---------------- device scratch (no allocation allowed) -------------------
__device__ float g_qkv[(size_t)Mv * C3v];
__device__ __half g_x16[(size_t)Mv * Cv];
__device__ __half g_wA[(size_t)C3v * Cv];     // transposed [3C, C] fp16
__device__ __half g_wP[(size_t)Cv * Cv];      // transposed [C, C] fp16
__device__ __half g_y_hi[(size_t)Mv * Cv];
__device__ __half g_y_lo[(size_t)Mv * Cv];

// ---------------------------------------------------------------------------
__device__ __forceinline__ void mma16816(float* c, const uint32_t* a,
                                         uint32_t b0, uint32_t b1) {
    asm volatile(
        "mma.sync.aligned.m16n8k16.row.col.f32.f16.f16.f32 "
        "{%0,%1,%2,%3}, {%4,%5,%6,%7}, {%8,%9}, {%0,%1,%2,%3};"
        : "+f"(c[0]), "+f"(c[1]), "+f"(c[2]), "+f"(c[3])
        : "r"(a[0]), "r"(a[1]), "r"(a[2]), "r"(a[3]), "r"(b0), "r"(b1));
}

__device__ __forceinline__ void ldsm4(uint32_t* r, uint32_t addr) {
    asm volatile("ldmatrix.sync.aligned.m8n8.x4.shared.b16 {%0,%1,%2,%3}, [%4];"
        : "=r"(r[0]), "=r"(r[1]), "=r"(r[2]), "=r"(r[3]) : "r"(addr));
}

__device__ __forceinline__ uint32_t smem_u32(const void* p) {
    uint32_t a;
    asm("{ .reg .u64 t; cvta.to.shared.u64 t, %1; cvt.u32.u64 %0, t; }" : "=r"(a) : "l"(p));
    return a;
}
#define CP16(dst, src) \
    asm volatile("cp.async.cg.shared.global [%0], [%1], 16;" :: "r"(dst), "l"(src))
#define CP_COMMIT() asm volatile("cp.async.commit_group;" ::: "memory")
#define CP_WAIT1()  asm volatile("cp.async.wait_group 1;" ::: "memory")
#define CP_WAIT0()  asm volatile("cp.async.wait_group 0;" ::: "memory")

__device__ __forceinline__ uint32_t pack_h(float a, float b) {
    __half2 t;
    t.x = __float2half_rn(a);
    t.y = __float2half_rn(b);
    return *(uint32_t*)&t;
}
__device__ __forceinline__ void split_pack_h(float a, float b, uint32_t& hi, uint32_t& lo) {
    __half ah = __float2half_rn(a);
    __half bh = __float2half_rn(b);
    __half2 t; t.x = ah; t.y = bh;
    hi = *(uint32_t*)&t;
    lo = pack_h(a - __half2float(ah), b - __half2float(bh));
}

// ---------------------------------------------------------------------------
// cvt fp32 -> fp16
__global__ void cvt_kernel(const float* __restrict__ in,
                           __half* __restrict__ out16, int n) {
    int i = (blockIdx.x * 256 + threadIdx.x) * 4;
    if (i >= n) return;
    float4 v = *(const float4*)(in + i);
    *(uint32_t*)(out16 + i)     = pack_h(v.x, v.y);
    *(uint32_t*)(out16 + i + 2) = pack_h(v.z, v.w);
}

// transpose + cvt: w[K,N] fp32 -> wT[N,K] fp16
__global__ void transpose_cvt(const float* __restrict__ w,
                              __half* __restrict__ t_, int K, int N) {
    __shared__ float st[32][33];
    const int n0 = blockIdx.x * 32, k0 = blockIdx.y * 32;
    const int tx = threadIdx.x, ty = threadIdx.y;          // (32, 8)
    #pragma unroll
    for (int i = 0; i < 4; i++)
        st[ty + 8 * i][tx] = w[(size_t)(k0 + ty + 8 * i) * N + n0 + tx];
    __syncthreads();
    #pragma unroll
    for (int i = 0; i < 4; i++)
        t_[(size_t)(n0 + ty + 8 * i) * K + k0 + tx] =
            __float2half_rn(st[tx][ty + 8 * i]);
}

// ---------------------------------------------------------------------------
// fp16 GEMM: C[M,N] = A[M,K] @ B[N,K]^T + bias, A in AP precision passes
// (AP=1: single fp16; AP=2: hi/lo split). 128x64 tile, BK=32, 8 warps,
// 2-stage cp.async, ldmatrix, 2 CTAs/SM.
// ---------------------------------------------------------------------------
#define GRS 40
#define GTA_BYTES 10240                // A tile: 128 * 40 * 2
#define GTB_BYTES 5120                 // B tile:  64 * 40 * 2

template <int AP>
__global__ __launch_bounds__(256, 2)
void gemm_mma(const __half* __restrict__ Ahi, const __half* __restrict__ Alo,
              const __half* __restrict__ Bm,
              const float* __restrict__ bias, float* __restrict__ Cmat,
              int N, int K) {
    constexpr int GB_OFF = 2 * AP * GTA_BYTES;
    extern __shared__ __align__(16) char gsm[];
    const uint32_t sb = smem_u32(gsm);

    const int tid = threadIdx.x;
    const int wid = tid >> 5, lane = tid & 31;
    const int g = lane >> 2, tig = lane & 3;
    const int bx = blockIdx.x, by = blockIdx.y;
    const int wm = (wid & 3) * 32;
    const int wn = (wid >> 2) * 32;

    const int aRow = lane & 15, aCol8 = (lane >> 4) * 8;
    const int bRow = ((lane >> 4) * 8) + (lane & 7);
    const int bCol8 = ((lane >> 3) & 1) * 8;

    const int lrow = tid >> 2;                  // 0..63
    const int lc8  = (tid & 3) * 8;

    float acc[2][4][4];
    #pragma unroll
    for (int mt = 0; mt < 2; mt++)
        #pragma unroll
        for (int nt = 0; nt < 4; nt++)
            #pragma unroll
            for (int j = 0; j < 4; j++) acc[mt][nt][j] = 0.f;

    const int nCh = K >> 5;

    auto load_chunk = [&](int c, int s) {
        const int k0 = c << 5;
        #pragma unroll
        for (int i = 0; i < 2; i++) {
            const int r = lrow + i * 64;
            const size_t ga = (size_t)(by * 128 + r) * K + k0 + lc8;
            const uint32_t ro = (uint32_t)(r * (GRS * 2) + lc8 * 2);
            CP16(sb + (s * AP + 0) * GTA_BYTES + ro, Ahi + ga);
            if (AP == 2)
                CP16(sb + (s * AP + 1) * GTA_BYTES + ro, Alo + ga);
        }
        {
            const size_t gb = (size_t)(bx * 64 + lrow) * K + k0 + lc8;
            const uint32_t ro = (uint32_t)(lrow * (GRS * 2) + lc8 * 2);
            CP16(sb + GB_OFF + s * GTB_BYTES + ro, Bm + gb);
        }
    };

    load_chunk(0, 0);
    CP_COMMIT();

    for (int c = 0; c < nCh; c++) {
        const int s = c & 1;
        if (c + 1 < nCh) {
            load_chunk(c + 1, s ^ 1);
            CP_COMMIT();
            CP_WAIT1();
        } else {
            CP_WAIT0();
        }
        __syncthreads();

        #pragma unroll
        for (int pass = 0; pass < AP; pass++) {
            const uint32_t abase = sb + (s * AP + pass) * GTA_BYTES;
            const uint32_t bbase = sb + GB_OFF + s * GTB_BYTES;
            #pragma unroll
            for (int ks = 0; ks < 2; ks++) {
                const int kc = ks * 16;
                uint32_t afr[2][4];
                #pragma unroll
                for (int mt = 0; mt < 2; mt++)
                    ldsm4(afr[mt], abase +
                          ((wm + mt * 16 + aRow) * GRS + kc + aCol8) * 2);
                #pragma unroll
                for (int p = 0; p < 2; p++) {
                    uint32_t bfr[4];
                    ldsm4(bfr, bbase +
                          ((wn + p * 16 + bRow) * GRS + kc + bCol8) * 2);
                    mma16816(acc[0][2 * p],     afr[0], bfr[0], bfr[1]);
                    mma16816(acc[1][2 * p],     afr[1], bfr[0], bfr[1]);
                    mma16816(acc[0][2 * p + 1], afr[0], bfr[2], bfr[3]);
                    mma16816(acc[1][2 * p + 1], afr[1], bfr[2], bfr[3]);
                }
            }
        }
        __syncthreads();
    }

    #pragma unroll
    for (int mt = 0; mt < 2; mt++) {
        #pragma unroll
        for (int nt = 0; nt < 4; nt++) {
            const int rg = by * 128 + wm + mt * 16 + g;
            const int cg = bx * 64 + wn + nt * 8 + tig * 2;
            const float bs0 = __ldg(bias + cg), bs1 = __ldg(bias + cg + 1);
            float2 v0, v1;
            v0.x = acc[mt][nt][0] + bs0;
            v0.y = acc[mt][nt][1] + bs1;
            v1.x = acc[mt][nt][2] + bs0;
            v1.y = acc[mt][nt][3] + bs1;
            *(float2*)(Cmat + (size_t)rg * N + cg)       = v0;
            *(float2*)(Cmat + (size_t)(rg + 8) * N + cg) = v1;
        }
    }
}

#define G_SMEM1 (2 * 1 * GTA_BYTES + 2 * GTB_BYTES)   // 30720
#define G_SMEM2 (2 * 2 * GTA_BYTES + 2 * GTB_BYTES)   // 51200

// ---------------------------------------------------------------------------
// fp16 single-pass causal flash attention: Q, K, P, V all single fp16,
// fp32 accum. Output y emitted as fp16 hi/lo (exact split) for the proj GEMM.
// ---------------------------------------------------------------------------
#define AKS 72               // K/V^T smem row stride (fp16)
#define A_OFF_KSH 0
#define A_OFF_VTH 9216
#define A_OFF_VST 18432      // fp32 staging 64x68
#define A_SMEM    (18432 + 64 * 68 * 4)   // 35840

__global__ __launch_bounds__(256, 2)
void attn_mma(const float* __restrict__ qkv,
              __half* __restrict__ yhi, __half* __restrict__ ylo) {
    extern __shared__ char sm[];
    const uint32_t sbase = smem_u32(sm);
    __half (*Ksh)[AKS] = (__half(*)[AKS])(sm + A_OFF_KSH);
    __half (*Vth)[AKS] = (__half(*)[AKS])(sm + A_OFF_VTH);
    float (*Vst)[68]   = (float(*)[68])(sm + A_OFF_VST);

    const int qt = (gridDim.x - 1) - blockIdx.x;   // heavy blocks first
    const int h  = blockIdx.y;
    const int b  = blockIdx.z;
    const int tid = threadIdx.x;
    const int wid = tid >> 5, lane = tid & 31;
    const int g = lane >> 2, tig = lane & 3;

    const int bRow = ((lane >> 4) * 8) + (lane & 7);
    const int bCol8 = ((lane >> 3) & 1) * 8;

    const int qr0 = qt * 128;
    const int row0 = qr0 + wid * 16 + g;
    const float* base = qkv + (size_t)b * Tv * C3v;

    uint32_t qh[4][4];
    {
        const float sc = 0.125f;
        #pragma unroll
        for (int ks = 0; ks < 4; ks++) {
            const int kc = ks * 16 + tig * 2;
            #pragma unroll
            for (int j = 0; j < 4; j++) {
                const int rr = (j & 1) ? row0 + 8 : row0;
                const int cc = kc + ((j >> 1) ? 8 : 0);
                float2 v = *(const float2*)(base + (size_t)rr * C3v + h * Dv + cc);
                qh[ks][j] = pack_h(v.x * sc, v.y * sc);
            }
        }
    }

    float acc_o[8][4];
    #pragma unroll
    for (int nt = 0; nt < 8; nt++)
        #pragma unroll
        for (int j = 0; j < 4; j++) acc_o[nt][j] = 0.f;
    float m0 = -INFINITY, m1 = -INFINITY, l0 = 0.f, l1 = 0.f;

    const int nkv = (qr0 >> 6) + 2;
    for (int kvb = 0; kvb < nkv; kvb++) {
        const int kv0 = kvb * 64;
        #pragma unroll
        for (int i = 0; i < 4; i++) {
            const int u = tid + i * 256;
            const int r = u >> 4, c4 = (u & 15) * 4;
            const float* rowp = base + (size_t)(kv0 + r) * C3v + h * Dv + c4;
            float4 kk = *(const float4*)(rowp + Cv);
            *(uint32_t*)&Ksh[r][c4]     = pack_h(kk.x, kk.y);
            *(uint32_t*)&Ksh[r][c4 + 2] = pack_h(kk.z, kk.w);
            *(float4*)&Vst[r][c4] = *(const float4*)(rowp + 2 * Cv);
        }
        __syncthreads();
        {
            const int d = tid >> 2;
            const int kq = (tid & 3) * 16;
            #pragma unroll
            for (int i = 0; i < 16; i += 2)
                *(uint32_t*)&Vth[d][kq + i] =
                    pack_h(Vst[kq + i][d], Vst[kq + i + 1][d]);
        }
        __syncthreads();

        if (kv0 <= qr0 + wid * 16 + 15) {
            float s_[8][4];
            #pragma unroll
            for (int nt = 0; nt < 8; nt++)
                #pragma unroll
                for (int j = 0; j < 4; j++) s_[nt][j] = 0.f;

            // S = Q K^T, single pass
            #pragma unroll
            for (int ks = 0; ks < 4; ks++) {
                const int kc = ks * 16;
                #pragma unroll
                for (int p = 0; p < 4; p++) {
                    uint32_t bfr[4];
                    ldsm4(bfr, sbase + A_OFF_KSH +
                          ((p * 16 + bRow) * AKS + kc + bCol8) * 2);
                    mma16816(s_[2 * p],     qh[ks], bfr[0], bfr[1]);
                    mma16816(s_[2 * p + 1], qh[ks], bfr[2], bfr[3]);
                }
            }

            float rmax0 = -INFINITY, rmax1 = -INFINITY;
            #pragma unroll
            for (int nt = 0; nt < 8; nt++) {
                const int colb = kv0 + nt * 8 + tig * 2;
                #pragma unroll
                for (int j = 0; j < 2; j++) {
                    if (colb + j > row0)     s_[nt][j]     = -INFINITY;
                    if (colb + j > row0 + 8) s_[nt][2 + j] = -INFINITY;
                    rmax0 = fmaxf(rmax0, s_[nt][j]);
                    rmax1 = fmaxf(rmax1, s_[nt][2 + j]);
                }
            }
            rmax0 = fmaxf(rmax0, __shfl_xor_sync(0xffffffff, rmax0, 1));
            rmax0 = fmaxf(rmax0, __shfl_xor_sync(0xffffffff, rmax0, 2));
            rmax1 = fmaxf(rmax1, __shfl_xor_sync(0xffffffff, rmax1, 1));
            rmax1 = fmaxf(rmax1, __shfl_xor_sync(0xffffffff, rmax1, 2));

            const float mn0 = fmaxf(m0, rmax0);
            const float mn1 = fmaxf(m1, rmax1);
            const float cr0 = __expf(m0 - mn0);
            const float cr1 = __expf(m1 - mn1);
            l0 *= cr0; l1 *= cr1;
            #pragma unroll
            for (int nt = 0; nt < 8; nt++) {
                acc_o[nt][0] *= cr0; acc_o[nt][1] *= cr0;
                acc_o[nt][2] *= cr1; acc_o[nt][3] *= cr1;
            }
            m0 = mn0; m1 = mn1;

            uint32_t ph[4][4];
            float rs0 = 0.f, rs1 = 0.f;
            #pragma unroll
            for (int kt = 0; kt < 4; kt++) {
                float p00, p01, p10, p11;
                p00 = __expf(s_[2 * kt][0] - mn0);
                p01 = __expf(s_[2 * kt][1] - mn0);
                p10 = __expf(s_[2 * kt][2] - mn1);
                p11 = __expf(s_[2 * kt][3] - mn1);
                rs0 += p00 + p01; rs1 += p10 + p11;
                ph[kt][0] = pack_h(p00, p01);
                ph[kt][1] = pack_h(p10, p11);
                p00 = __expf(s_[2 * kt + 1][0] - mn0);
                p01 = __expf(s_[2 * kt + 1][1] - mn0);
                p10 = __expf(s_[2 * kt + 1][2] - mn1);
                p11 = __expf(s_[2 * kt + 1][3] - mn1);
                rs0 += p00 + p01; rs1 += p10 + p11;
                ph[kt][2] = pack_h(p00, p01);
                ph[kt][3] = pack_h(p10, p11);
            }
            rs0 += __shfl_xor_sync(0xffffffff, rs0, 1);
            rs0 += __shfl_xor_sync(0xffffffff, rs0, 2);
            rs1 += __shfl_xor_sync(0xffffffff, rs1, 1);
            rs1 += __shfl_xor_sync(0xffffffff, rs1, 2);
            l0 += rs0; l1 += rs1;

            // O += P V, single pass
            #pragma unroll
            for (int kt = 0; kt < 4; kt++) {
                const int kc = kt * 16;
                #pragma unroll
                for (int p = 0; p < 4; p++) {
                    uint32_t bfr[4];
                    ldsm4(bfr, sbase + A_OFF_VTH +
                          ((p * 16 + bRow) * AKS + kc + bCol8) * 2);
                    mma16816(acc_o[2 * p],     ph[kt], bfr[0], bfr[1]);
                    mma16816(acc_o[2 * p + 1], ph[kt], bfr[2], bfr[3]);
                }
            }
        }
        __syncthreads();
    }

    const float i0 = 1.f / l0, i1 = 1.f / l1;
    #pragma unroll
    for (int nt = 0; nt < 8; nt++) {
        const int d = nt * 8 + tig * 2;
        const size_t o0 = ((size_t)b * Tv + row0) * Cv + h * Dv + d;
        const size_t o1 = o0 + (size_t)8 * Cv;
        uint32_t hh, lo;
        split_pack_h(acc_o[nt][0] * i0, acc_o[nt][1] * i0, hh, lo);
        *(uint32_t*)(yhi + o0) = hh;
        *(uint32_t*)(ylo + o0) = lo;
        split_pack_h(acc_o[nt][2] * i1, acc_o[nt][3] * i1, hh, lo);
        *(uint32_t*)(yhi + o1) = hh;
        *(uint32_t*)(ylo + o1) = lo;
    }
}

// ---------------------------------------------------------------------------
extern "C" void kernel_launch(void* const* d_in, const int* in_sizes, int n_in,
                              void* d_out, int out_size) {
    const float* x      = (const float*)d_in[0];
    const float* w_attn = (const float*)d_in[1];
    const float* b_attn = (const float*)d_in[2];
    const float* w_proj = (const float*)d_in[3];
    const float* b_proj = (const float*)d_in[4];
    float* out = (float*)d_out;

    float* qkv; __half *x16, *wA, *wP, *yh, *yl;
    cudaGetSymbolAddress((void**)&qkv, g_qkv);
    cudaGetSymbolAddress((void**)&x16, g_x16);
    cudaGetSymbolAddress((void**)&wA, g_wA);
    cudaGetSymbolAddress((void**)&wP, g_wP);
    cudaGetSymbolAddress((void**)&yh, g_y_hi);
    cudaGetSymbolAddress((void**)&yl, g_y_lo);

    cudaFuncSetAttribute(gemm_mma<1>, cudaFuncAttributeMaxDynamicSharedMemorySize, G_SMEM1);
    cudaFuncSetAttribute(gemm_mma<2>, cudaFuncAttributeMaxDynamicSharedMemorySize, G_SMEM2);
    cudaFuncSetAttribute(attn_mma, cudaFuncAttributeMaxDynamicSharedMemorySize, A_SMEM);

    const int nx = Mv * Cv;
    cvt_kernel<<<(nx / 4 + 255) / 256, 256>>>(x, x16, nx);
    transpose_cvt<<<dim3(C3v / 32, Cv / 32), dim3(32, 8)>>>(w_attn, wA, Cv, C3v);
    transpose_cvt<<<dim3(Cv / 32, Cv / 32), dim3(32, 8)>>>(w_proj, wP, Cv, Cv);

    // 1) qkv = x @ w_attn + b_attn   (1-pass fp16 A)
    gemm_mma<1><<<dim3(C3v / 64, Mv / 128), 256, G_SMEM1>>>(
        x16, nullptr, wA, b_attn, qkv, C3v, Cv);
    // 2) causal flash attention (single-pass S and PV)
    attn_mma<<<dim3(Tv / 128, Hv, Bv), 256, A_SMEM>>>(qkv, yh, yl);
    // 3) out = y @ w_proj + b_proj   (2-pass: exact y hi/lo split)
    gemm_mma<2><<<dim3(Cv / 64, Mv / 128), 256, G_SMEM2>>>(
        yh, yl, wP, b_proj, out, Cv, Cv);
}

// round 12
// speedup vs baseline: 2.9401x; 1.1919x over previous
#include <cuda_runtime.h>
#include <cuda_fp16.h>
#include <math.h>
#include <stdint.h>

// Problem constants: B=4, T=2048, C=768, H=12, D=64
#define Bv 4
#define Tv 2048
#define Cv 768
#define Hv 12
#define Dv 64
#define C3v (3 * Cv)     // 2304
#define Mv (Bv * Tv)     // 8192

// ---------------- device scratch (no allocation allowed) -------------------
__device__ float g_qkv[(size_t)Mv * C3v];
__device__ __half g_x16[(size_t)Mv * Cv];
__device__ __half g_wA[(size_t)C3v * Cv];     // transposed [3C, C] fp16
__device__ __half g_wP[(size_t)Cv * Cv];      // transposed [C, C] fp16
__device__ __half g_y16[(size_t)Mv * Cv];

// ---------------------------------------------------------------------------
__device__ __forceinline__ void mma16816(float* c, const uint32_t* a,
                                         uint32_t b0, uint32_t b1) {
    asm volatile(
        "mma.sync.aligned.m16n8k16.row.col.f32.f16.f16.f32 "
        "{%0,%1,%2,%3}, {%4,%5,%6,%7}, {%8,%9}, {%0,%1,%2,%3};"
        : "+f"(c[0]), "+f"(c[1]), "+f"(c[2]), "+f"(c[3])
        : "r"(a[0]), "r"(a[1]), "r"(a[2]), "r"(a[3]), "r"(b0), "r"(b1));
}

__device__ __forceinline__ void ldsm4(uint32_t* r, uint32_t addr) {
    asm volatile("ldmatrix.sync.aligned.m8n8.x4.shared.b16 {%0,%1,%2,%3}, [%4];"
        : "=r"(r[0]), "=r"(r[1]), "=r"(r[2]), "=r"(r[3]) : "r"(addr));
}

__device__ __forceinline__ uint32_t smem_u32(const void* p) {
    uint32_t a;
    asm("{ .reg .u64 t; cvta.to.shared.u64 t, %1; cvt.u32.u64 %0, t; }" : "=r"(a) : "l"(p));
    return a;
}
#define CP16(dst, src) \
    asm volatile("cp.async.cg.shared.global [%0], [%1], 16;" :: "r"(dst), "l"(src))
#define CP_COMMIT() asm volatile("cp.async.commit_group;" ::: "memory")
#define CP_WAIT1()  asm volatile("cp.async.wait_group 1;" ::: "memory")
#define CP_WAIT0()  asm volatile("cp.async.wait_group 0;" ::: "memory")

__device__ __forceinline__ uint32_t pack_h(float a, float b) {
    __half2 t;
    t.x = __float2half_rn(a);
    t.y = __float2half_rn(b);
    return *(uint32_t*)&t;
}

// ---------------------------------------------------------------------------
// cvt fp32 -> fp16
__global__ void cvt_kernel(const float* __restrict__ in,
                           __half* __restrict__ out16, int n) {
    int i = (blockIdx.x * 256 + threadIdx.x) * 4;
    if (i >= n) return;
    float4 v = *(const float4*)(in + i);
    *(uint32_t*)(out16 + i)     = pack_h(v.x, v.y);
    *(uint32_t*)(out16 + i + 2) = pack_h(v.z, v.w);
}

// transpose + cvt: w[K,N] fp32 -> wT[N,K] fp16
__global__ void transpose_cvt(const float* __restrict__ w,
                              __half* __restrict__ t_, int K, int N) {
    __shared__ float st[32][33];
    const int n0 = blockIdx.x * 32, k0 = blockIdx.y * 32;
    const int tx = threadIdx.x, ty = threadIdx.y;          // (32, 8)
    #pragma unroll
    for (int i = 0; i < 4; i++)
        st[ty + 8 * i][tx] = w[(size_t)(k0 + ty + 8 * i) * N + n0 + tx];
    __syncthreads();
    #pragma unroll
    for (int i = 0; i < 4; i++)
        t_[(size_t)(n0 + ty + 8 * i) * K + k0 + tx] =
            __float2half_rn(st[tx][ty + 8 * i]);
}

// ---------------------------------------------------------------------------
// fp16 GEMM: C[M,N] = A[M,K] @ B[N,K]^T + bias.
// 128x64 tile, BK=64, 8 warps (4Mx2N), 2-stage cp.async, ldmatrix, 2 CTAs/SM.
// smem rows: 72 halfwords (144B) — 16B-aligned, conflict-free ldmatrix.
// ---------------------------------------------------------------------------
#define GRS 72
#define GTA_BYTES 18432                // A tile: 128 * 72 * 2
#define GTB_BYTES 9216                 // B tile:  64 * 72 * 2
#define GB_OFF    (2 * GTA_BYTES)      // 36864
#define G_SMEM    (GB_OFF + 2 * GTB_BYTES)   // 55296

__global__ __launch_bounds__(256, 2)
void gemm_mma(const __half* __restrict__ Am, const __half* __restrict__ Bm,
              const float* __restrict__ bias, float* __restrict__ Cmat,
              int N, int K) {
    extern __shared__ __align__(16) char gsm[];
    const uint32_t sb = smem_u32(gsm);

    const int tid = threadIdx.x;
    const int wid = tid >> 5, lane = tid & 31;
    const int g = lane >> 2, tig = lane & 3;
    const int bx = blockIdx.x, by = blockIdx.y;
    const int wm = (wid & 3) * 32;
    const int wn = (wid >> 2) * 32;

    const int aRow = lane & 15, aCol8 = (lane >> 4) * 8;
    const int bRow = ((lane >> 4) * 8) + (lane & 7);
    const int bCol8 = ((lane >> 3) & 1) * 8;

    float acc[2][4][4];
    #pragma unroll
    for (int mt = 0; mt < 2; mt++)
        #pragma unroll
        for (int nt = 0; nt < 4; nt++)
            #pragma unroll
            for (int j = 0; j < 4; j++) acc[mt][nt][j] = 0.f;

    const int nCh = K >> 6;                     // BK = 64

    auto load_chunk = [&](int c, int s) {
        const int k0 = c << 6;
        // A: 128 rows x 128B = 1024 16B-units, 4/thread
        #pragma unroll
        for (int i = 0; i < 4; i++) {
            const int u = tid + i * 256;
            const int r = u >> 3, c8 = (u & 7) * 8;
            const size_t ga = (size_t)(by * 128 + r) * K + k0 + c8;
            CP16(sb + s * GTA_BYTES + (uint32_t)(r * 144 + c8 * 2), Am + ga);
        }
        // B: 64 rows x 128B = 512 units, 2/thread
        #pragma unroll
        for (int i = 0; i < 2; i++) {
            const int u = tid + i * 256;
            const int r = u >> 3, c8 = (u & 7) * 8;
            const size_t gb = (size_t)(bx * 64 + r) * K + k0 + c8;
            CP16(sb + GB_OFF + s * GTB_BYTES + (uint32_t)(r * 144 + c8 * 2), Bm + gb);
        }
    };

    load_chunk(0, 0);
    CP_COMMIT();

    for (int c = 0; c < nCh; c++) {
        const int s = c & 1;
        if (c + 1 < nCh) {
            load_chunk(c + 1, s ^ 1);
            CP_COMMIT();
            CP_WAIT1();
        } else {
            CP_WAIT0();
        }
        __syncthreads();

        const uint32_t abase = sb + s * GTA_BYTES;
        const uint32_t bbase = sb + GB_OFF + s * GTB_BYTES;
        #pragma unroll
        for (int ks = 0; ks < 4; ks++) {
            const int kc = ks * 16;
            uint32_t afr[2][4];
            #pragma unroll
            for (int mt = 0; mt < 2; mt++)
                ldsm4(afr[mt], abase +
                      ((wm + mt * 16 + aRow) * GRS + kc + aCol8) * 2);
            #pragma unroll
            for (int p = 0; p < 2; p++) {
                uint32_t bfr[4];
                ldsm4(bfr, bbase +
                      ((wn + p * 16 + bRow) * GRS + kc + bCol8) * 2);
                mma16816(acc[0][2 * p],     afr[0], bfr[0], bfr[1]);
                mma16816(acc[1][2 * p],     afr[1], bfr[0], bfr[1]);
                mma16816(acc[0][2 * p + 1], afr[0], bfr[2], bfr[3]);
                mma16816(acc[1][2 * p + 1], afr[1], bfr[2], bfr[3]);
            }
        }
        __syncthreads();
    }

    #pragma unroll
    for (int mt = 0; mt < 2; mt++) {
        #pragma unroll
        for (int nt = 0; nt < 4; nt++) {
            const int rg = by * 128 + wm + mt * 16 + g;
            const int cg = bx * 64 + wn + nt * 8 + tig * 2;
            const float bs0 = __ldg(bias + cg), bs1 = __ldg(bias + cg + 1);
            float2 v0, v1;
            v0.x = acc[mt][nt][0] + bs0;
            v0.y = acc[mt][nt][1] + bs1;
            v1.x = acc[mt][nt][2] + bs0;
            v1.y = acc[mt][nt][3] + bs1;
            *(float2*)(Cmat + (size_t)rg * N + cg)       = v0;
            *(float2*)(Cmat + (size_t)(rg + 8) * N + cg) = v1;
        }
    }
}

// ---------------------------------------------------------------------------
// fp16 single-pass causal flash attention (R11-proven); y emitted single fp16.
// ---------------------------------------------------------------------------
#define AKS 72               // K/V^T smem row stride (fp16)
#define A_OFF_KSH 0
#define A_OFF_VTH 9216
#define A_OFF_VST 18432      // fp32 staging 64x68
#define A_SMEM    (18432 + 64 * 68 * 4)   // 35840

__global__ __launch_bounds__(256, 2)
void attn_mma(const float* __restrict__ qkv, __half* __restrict__ y16) {
    extern __shared__ char sm[];
    const uint32_t sbase = smem_u32(sm);
    __half (*Ksh)[AKS] = (__half(*)[AKS])(sm + A_OFF_KSH);
    __half (*Vth)[AKS] = (__half(*)[AKS])(sm + A_OFF_VTH);
    float (*Vst)[68]   = (float(*)[68])(sm + A_OFF_VST);

    const int qt = (gridDim.x - 1) - blockIdx.x;   // heavy blocks first
    const int h  = blockIdx.y;
    const int b  = blockIdx.z;
    const int tid = threadIdx.x;
    const int wid = tid >> 5, lane = tid & 31;
    const int g = lane >> 2, tig = lane & 3;

    const int bRow = ((lane >> 4) * 8) + (lane & 7);
    const int bCol8 = ((lane >> 3) & 1) * 8;

    const int qr0 = qt * 128;
    const int row0 = qr0 + wid * 16 + g;
    const float* base = qkv + (size_t)b * Tv * C3v;

    uint32_t qh[4][4];
    {
        const float sc = 0.125f;
        #pragma unroll
        for (int ks = 0; ks < 4; ks++) {
            const int kc = ks * 16 + tig * 2;
            #pragma unroll
            for (int j = 0; j < 4; j++) {
                const int rr = (j & 1) ? row0 + 8 : row0;
                const int cc = kc + ((j >> 1) ? 8 : 0);
                float2 v = *(const float2*)(base + (size_t)rr * C3v + h * Dv + cc);
                qh[ks][j] = pack_h(v.x * sc, v.y * sc);
            }
        }
    }

    float acc_o[8][4];
    #pragma unroll
    for (int nt = 0; nt < 8; nt++)
        #pragma unroll
        for (int j = 0; j < 4; j++) acc_o[nt][j] = 0.f;
    float m0 = -INFINITY, m1 = -INFINITY, l0 = 0.f, l1 = 0.f;

    const int nkv = (qr0 >> 6) + 2;
    for (int kvb = 0; kvb < nkv; kvb++) {
        const int kv0 = kvb * 64;
        #pragma unroll
        for (int i = 0; i < 4; i++) {
            const int u = tid + i * 256;
            const int r = u >> 4, c4 = (u & 15) * 4;
            const float* rowp = base + (size_t)(kv0 + r) * C3v + h * Dv + c4;
            float4 kk = *(const float4*)(rowp + Cv);
            *(uint32_t*)&Ksh[r][c4]     = pack_h(kk.x, kk.y);
            *(uint32_t*)&Ksh[r][c4 + 2] = pack_h(kk.z, kk.w);
            *(float4*)&Vst[r][c4] = *(const float4*)(rowp + 2 * Cv);
        }
        __syncthreads();
        {
            const int d = tid >> 2;
            const int kq = (tid & 3) * 16;
            #pragma unroll
            for (int i = 0; i < 16; i += 2)
                *(uint32_t*)&Vth[d][kq + i] =
                    pack_h(Vst[kq + i][d], Vst[kq + i + 1][d]);
        }
        __syncthreads();

        if (kv0 <= qr0 + wid * 16 + 15) {
            float s_[8][4];
            #pragma unroll
            for (int nt = 0; nt < 8; nt++)
                #pragma unroll
                for (int j = 0; j < 4; j++) s_[nt][j] = 0.f;

            #pragma unroll
            for (int ks = 0; ks < 4; ks++) {
                const int kc = ks * 16;
                #pragma unroll
                for (int p = 0; p < 4; p++) {
                    uint32_t bfr[4];
                    ldsm4(bfr, sbase + A_OFF_KSH +
                          ((p * 16 + bRow) * AKS + kc + bCol8) * 2);
                    mma16816(s_[2 * p],     qh[ks], bfr[0], bfr[1]);
                    mma16816(s_[2 * p + 1], qh[ks], bfr[2], bfr[3]);
                }
            }

            float rmax0 = -INFINITY, rmax1 = -INFINITY;
            #pragma unroll
            for (int nt = 0; nt < 8; nt++) {
                const int colb = kv0 + nt * 8 + tig * 2;
                #pragma unroll
                for (int j = 0; j < 2; j++) {
                    if (colb + j > row0)     s_[nt][j]     = -INFINITY;
                    if (colb + j > row0 + 8) s_[nt][2 + j] = -INFINITY;
                    rmax0 = fmaxf(rmax0, s_[nt][j]);
                    rmax1 = fmaxf(rmax1, s_[nt][2 + j]);
                }
            }
            rmax0 = fmaxf(rmax0, __shfl_xor_sync(0xffffffff, rmax0, 1));
            rmax0 = fmaxf(rmax0, __shfl_xor_sync(0xffffffff, rmax0, 2));
            rmax1 = fmaxf(rmax1, __shfl_xor_sync(0xffffffff, rmax1, 1));
            rmax1 = fmaxf(rmax1, __shfl_xor_sync(0xffffffff, rmax1, 2));

            const float mn0 = fmaxf(m0, rmax0);
            const float mn1 = fmaxf(m1, rmax1);
            const float cr0 = __expf(m0 - mn0);
            const float cr1 = __expf(m1 - mn1);
            l0 *= cr0; l1 *= cr1;
            #pragma unroll
            for (int nt = 0; nt < 8; nt++) {
                acc_o[nt][0] *= cr0; acc_o[nt][1] *= cr0;
                acc_o[nt][2] *= cr1; acc_o[nt][3] *= cr1;
            }
            m0 = mn0; m1 = mn1;

            uint32_t ph[4][4];
            float rs0 = 0.f, rs1 = 0.f;
            #pragma unroll
            for (int kt = 0; kt < 4; kt++) {
                float p00, p01, p10, p11;
                p00 = __expf(s_[2 * kt][0] - mn0);
                p01 = __expf(s_[2 * kt][1] - mn0);
                p10 = __expf(s_[2 * kt][2] - mn1);
                p11 = __expf(s_[2 * kt][3] - mn1);
                rs0 += p00 + p01; rs1 += p10 + p11;
                ph[kt][0] = pack_h(p00, p01);
                ph[kt][1] = pack_h(p10, p11);
                p00 = __expf(s_[2 * kt + 1][0] - mn0);
                p01 = __expf(s_[2 * kt + 1][1] - mn0);
                p10 = __expf(s_[2 * kt + 1][2] - mn1);
                p11 = __expf(s_[2 * kt + 1][3] - mn1);
                rs0 += p00 + p01; rs1 += p10 + p11;
                ph[kt][2] = pack_h(p00, p01);
                ph[kt][3] = pack_h(p10, p11);
            }
            rs0 += __shfl_xor_sync(0xffffffff, rs0, 1);
            rs0 += __shfl_xor_sync(0xffffffff, rs0, 2);
            rs1 += __shfl_xor_sync(0xffffffff, rs1, 1);
            rs1 += __shfl_xor_sync(0xffffffff, rs1, 2);
            l0 += rs0; l1 += rs1;

            #pragma unroll
            for (int kt = 0; kt < 4; kt++) {
                const int kc = kt * 16;
                #pragma unroll
                for (int p = 0; p < 4; p++) {
                    uint32_t bfr[4];
                    ldsm4(bfr, sbase + A_OFF_VTH +
                          ((p * 16 + bRow) * AKS + kc + bCol8) * 2);
                    mma16816(acc_o[2 * p],     ph[kt], bfr[0], bfr[1]);
                    mma16816(acc_o[2 * p + 1], ph[kt], bfr[2], bfr[3]);
                }
            }
        }
        __syncthreads();
    }

    const float i0 = 1.f / l0, i1 = 1.f / l1;
    #pragma unroll
    for (int nt = 0; nt < 8; nt++) {
        const int d = nt * 8 + tig * 2;
        const size_t o0 = ((size_t)b * Tv + row0) * Cv + h * Dv + d;
        const size_t o1 = o0 + (size_t)8 * Cv;
        *(uint32_t*)(y16 + o0) = pack_h(acc_o[nt][0] * i0, acc_o[nt][1] * i0);
        *(uint32_t*)(y16 + o1) = pack_h(acc_o[nt][2] * i1, acc_o[nt][3] * i1);
    }
}

// ---------------------------------------------------------------------------
extern "C" void kernel_launch(void* const* d_in, const int* in_sizes, int n_in,
                              void* d_out, int out_size) {
    const float* x      = (const float*)d_in[0];
    const float* w_attn = (const float*)d_in[1];
    const float* b_attn = (const float*)d_in[2];
    const float* w_proj = (const float*)d_in[3];
    const float* b_proj = (const float*)d_in[4];
    float* out = (float*)d_out;

    float* qkv; __half *x16, *wA, *wP, *y16;
    cudaGetSymbolAddress((void**)&qkv, g_qkv);
    cudaGetSymbolAddress((void**)&x16, g_x16);
    cudaGetSymbolAddress((void**)&wA, g_wA);
    cudaGetSymbolAddress((void**)&wP, g_wP);
    cudaGetSymbolAddress((void**)&y16, g_y16);

    cudaFuncSetAttribute(gemm_mma, cudaFuncAttributeMaxDynamicSharedMemorySize, G_SMEM);
    cudaFuncSetAttribute(attn_mma, cudaFuncAttributeMaxDynamicSharedMemorySize, A_SMEM);

    const int nx = Mv * Cv;
    cvt_kernel<<<(nx / 4 + 255) / 256, 256>>>(x, x16, nx);
    transpose_cvt<<<dim3(C3v / 32, Cv / 32), dim3(32, 8)>>>(w_attn, wA, Cv, C3v);
    transpose_cvt<<<dim3(Cv / 32, Cv / 32), dim3(32, 8)>>>(w_proj, wP, Cv, Cv);

    // 1) qkv = x @ w_attn + b_attn   (fp16, BK=64)
    gemm_mma<<<dim3(C3v / 64, Mv / 128), 256, G_SMEM>>>(x16, wA, b_attn, qkv, C3v, Cv);
    // 2) causal flash attention (single-pass S and PV)
    attn_mma<<<dim3(Tv / 128, Hv, Bv), 256, A_SMEM>>>(qkv, y16);
    // 3) out = y @ w_proj + b_proj   (fp16, BK=64)
    gemm_mma<<<dim3(Cv / 64, Mv / 128), 256, G_SMEM>>>(y16, wP, b_proj, out, Cv, Cv);
}

// round 13
// speedup vs baseline: 3.3445x; 1.1375x over previous
#include <cuda_runtime.h>
#include <cuda_fp16.h>
#include <math.h>
#include <stdint.h>

// Problem constants: B=4, T=2048, C=768, H=12, D=64
#define Bv 4
#define Tv 2048
#define Cv 768
#define Hv 12
#define Dv 64
#define C3v (3 * Cv)     // 2304
#define Mv (Bv * Tv)     // 8192

// ---------------- device scratch (no allocation allowed) -------------------
__device__ __half g_x16[(size_t)Mv * Cv];
__device__ __half g_wA[(size_t)C3v * Cv];     // transposed [3C, C] fp16
__device__ __half g_wP[(size_t)Cv * Cv];      // transposed [C, C] fp16
__device__ __half g_q16[(size_t)Mv * Cv];     // [b,h,t,d], pre-scaled by 1/8
__device__ __half g_k16[(size_t)Mv * Cv];     // [b,h,t,d]
__device__ __half g_vt16[(size_t)Mv * Cv];    // [b,h,d,t]  (V transposed)
__device__ __half g_y16[(size_t)Mv * Cv];     // [b,t,h*d]

// ---------------------------------------------------------------------------
__device__ __forceinline__ void mma16816(float* c, const uint32_t* a,
                                         uint32_t b0, uint32_t b1) {
    asm volatile(
        "mma.sync.aligned.m16n8k16.row.col.f32.f16.f16.f32 "
        "{%0,%1,%2,%3}, {%4,%5,%6,%7}, {%8,%9}, {%0,%1,%2,%3};"
        : "+f"(c[0]), "+f"(c[1]), "+f"(c[2]), "+f"(c[3])
        : "r"(a[0]), "r"(a[1]), "r"(a[2]), "r"(a[3]), "r"(b0), "r"(b1));
}

__device__ __forceinline__ void ldsm4(uint32_t* r, uint32_t addr) {
    asm volatile("ldmatrix.sync.aligned.m8n8.x4.shared.b16 {%0,%1,%2,%3}, [%4];"
        : "=r"(r[0]), "=r"(r[1]), "=r"(r[2]), "=r"(r[3]) : "r"(addr));
}

__device__ __forceinline__ uint32_t smem_u32(const void* p) {
    uint32_t a;
    asm("{ .reg .u64 t; cvta.to.shared.u64 t, %1; cvt.u32.u64 %0, t; }" : "=r"(a) : "l"(p));
    return a;
}
#define CP16(dst, src) \
    asm volatile("cp.async.cg.shared.global [%0], [%1], 16;" :: "r"(dst), "l"(src))
#define CP_COMMIT() asm volatile("cp.async.commit_group;" ::: "memory")
#define CP_WAIT1()  asm volatile("cp.async.wait_group 1;" ::: "memory")
#define CP_WAIT0()  asm volatile("cp.async.wait_group 0;" ::: "memory")

__device__ __forceinline__ uint32_t pack_h(float a, float b) {
    __half2 t;
    t.x = __float2half_rn(a);
    t.y = __float2half_rn(b);
    return *(uint32_t*)&t;
}

// ---------------------------------------------------------------------------
__global__ void cvt_kernel(const float* __restrict__ in,
                           __half* __restrict__ out16, int n) {
    int i = (blockIdx.x * 256 + threadIdx.x) * 4;
    if (i >= n) return;
    float4 v = *(const float4*)(in + i);
    *(uint32_t*)(out16 + i)     = pack_h(v.x, v.y);
    *(uint32_t*)(out16 + i + 2) = pack_h(v.z, v.w);
}

__global__ void transpose_cvt(const float* __restrict__ w,
                              __half* __restrict__ t_, int K, int N) {
    __shared__ float st[32][33];
    const int n0 = blockIdx.x * 32, k0 = blockIdx.y * 32;
    const int tx = threadIdx.x, ty = threadIdx.y;          // (32, 8)
    #pragma unroll
    for (int i = 0; i < 4; i++)
        st[ty + 8 * i][tx] = w[(size_t)(k0 + ty + 8 * i) * N + n0 + tx];
    __syncthreads();
    #pragma unroll
    for (int i = 0; i < 4; i++)
        t_[(size_t)(n0 + ty + 8 * i) * K + k0 + tx] =
            __float2half_rn(st[tx][ty + 8 * i]);
}

// ---------------------------------------------------------------------------
// fp16 GEMM: 128x64 tile, BK=64, 8 warps (4Mx2N), 2-stage cp.async, ldmatrix.
// MODE 0: C = A@B^T + bias -> fp32 Cmat.
// MODE 1: QKV epilogue -> scatter fp16 to q16 (scaled), k16, vt16 (transposed).
// ---------------------------------------------------------------------------
#define GRS 72
#define GTA_BYTES 18432                // A tile: 128 * 72 * 2
#define GTB_BYTES 9216                 // B tile:  64 * 72 * 2
#define GB_OFF    (2 * GTA_BYTES)      // 36864
#define G_SMEM    (GB_OFF + 2 * GTB_BYTES)   // 55296

template <int MODE>
__global__ __launch_bounds__(256, 2)
void gemm_mma(const __half* __restrict__ Am, const __half* __restrict__ Bm,
              const float* __restrict__ bias, float* __restrict__ Cmat,
              __half* __restrict__ q16, __half* __restrict__ k16,
              __half* __restrict__ vt16, int N, int K) {
    extern __shared__ __align__(16) char gsm[];
    const uint32_t sb = smem_u32(gsm);

    const int tid = threadIdx.x;
    const int wid = tid >> 5, lane = tid & 31;
    const int g = lane >> 2, tig = lane & 3;
    const int bx = blockIdx.x, by = blockIdx.y;
    const int wm = (wid & 3) * 32;
    const int wn = (wid >> 2) * 32;

    const int aRow = lane & 15, aCol8 = (lane >> 4) * 8;
    const int bRow = ((lane >> 4) * 8) + (lane & 7);
    const int bCol8 = ((lane >> 3) & 1) * 8;

    float acc[2][4][4];
    #pragma unroll
    for (int mt = 0; mt < 2; mt++)
        #pragma unroll
        for (int nt = 0; nt < 4; nt++)
            #pragma unroll
            for (int j = 0; j < 4; j++) acc[mt][nt][j] = 0.f;

    const int nCh = K >> 6;                     // BK = 64

    auto load_chunk = [&](int c, int s) {
        const int k0 = c << 6;
        #pragma unroll
        for (int i = 0; i < 4; i++) {
            const int u = tid + i * 256;
            const int r = u >> 3, c8 = (u & 7) * 8;
            const size_t ga = (size_t)(by * 128 + r) * K + k0 + c8;
            CP16(sb + s * GTA_BYTES + (uint32_t)(r * 144 + c8 * 2), Am + ga);
        }
        #pragma unroll
        for (int i = 0; i < 2; i++) {
            const int u = tid + i * 256;
            const int r = u >> 3, c8 = (u & 7) * 8;
            const size_t gb = (size_t)(bx * 64 + r) * K + k0 + c8;
            CP16(sb + GB_OFF + s * GTB_BYTES + (uint32_t)(r * 144 + c8 * 2), Bm + gb);
        }
    };

    load_chunk(0, 0);
    CP_COMMIT();

    for (int c = 0; c < nCh; c++) {
        const int s = c & 1;
        if (c + 1 < nCh) {
            load_chunk(c + 1, s ^ 1);
            CP_COMMIT();
            CP_WAIT1();
        } else {
            CP_WAIT0();
        }
        __syncthreads();

        const uint32_t abase = sb + s * GTA_BYTES;
        const uint32_t bbase = sb + GB_OFF + s * GTB_BYTES;
        #pragma unroll
        for (int ks = 0; ks < 4; ks++) {
            const int kc = ks * 16;
            uint32_t afr[2][4];
            #pragma unroll
            for (int mt = 0; mt < 2; mt++)
                ldsm4(afr[mt], abase +
                      ((wm + mt * 16 + aRow) * GRS + kc + aCol8) * 2);
            #pragma unroll
            for (int p = 0; p < 2; p++) {
                uint32_t bfr[4];
                ldsm4(bfr, bbase +
                      ((wn + p * 16 + bRow) * GRS + kc + bCol8) * 2);
                mma16816(acc[0][2 * p],     afr[0], bfr[0], bfr[1]);
                mma16816(acc[1][2 * p],     afr[1], bfr[0], bfr[1]);
                mma16816(acc[0][2 * p + 1], afr[0], bfr[2], bfr[3]);
                mma16816(acc[1][2 * p + 1], afr[1], bfr[2], bfr[3]);
            }
        }
        __syncthreads();
    }

    if (MODE == 0) {
        #pragma unroll
        for (int mt = 0; mt < 2; mt++) {
            #pragma unroll
            for (int nt = 0; nt < 4; nt++) {
                const int rg = by * 128 + wm + mt * 16 + g;
                const int cg = bx * 64 + wn + nt * 8 + tig * 2;
                const float bs0 = __ldg(bias + cg), bs1 = __ldg(bias + cg + 1);
                float2 v0, v1;
                v0.x = acc[mt][nt][0] + bs0;
                v0.y = acc[mt][nt][1] + bs1;
                v1.x = acc[mt][nt][2] + bs0;
                v1.y = acc[mt][nt][3] + bs1;
                *(float2*)(Cmat + (size_t)rg * N + cg)       = v0;
                *(float2*)(Cmat + (size_t)(rg + 8) * N + cg) = v1;
            }
        }
    } else {
        const int reg3 = bx / Hv;       // 0=Q, 1=K, 2=V
        const int h    = bx % Hv;
        #pragma unroll
        for (int mt = 0; mt < 2; mt++) {
            #pragma unroll
            for (int nt = 0; nt < 4; nt++) {
                const int rg = by * 128 + wm + mt * 16 + g;
                const int bb = rg >> 11, t = rg & 2047;
                const int d = wn + nt * 8 + tig * 2;
                const int cg = bx * 64 + d;
                const float bs0 = __ldg(bias + cg), bs1 = __ldg(bias + cg + 1);
                const float v0 = acc[mt][nt][0] + bs0;
                const float v1 = acc[mt][nt][1] + bs1;
                const float v2 = acc[mt][nt][2] + bs0;
                const float v3 = acc[mt][nt][3] + bs1;
                if (reg3 == 0) {
                    const size_t o = ((size_t)(bb * Hv + h) * Tv + t) * Dv + d;
                    *(uint32_t*)(q16 + o)           = pack_h(v0 * 0.125f, v1 * 0.125f);
                    *(uint32_t*)(q16 + o + 8 * Dv)  = pack_h(v2 * 0.125f, v3 * 0.125f);
                } else if (reg3 == 1) {
                    const size_t o = ((size_t)(bb * Hv + h) * Tv + t) * Dv + d;
                    *(uint32_t*)(k16 + o)           = pack_h(v0, v1);
                    *(uint32_t*)(k16 + o + 8 * Dv)  = pack_h(v2, v3);
                } else {
                    const size_t o = ((size_t)(bb * Hv + h) * Dv + d) * Tv + t;
                    vt16[o]          = __float2half_rn(v0);
                    vt16[o + Tv]     = __float2half_rn(v1);
                    vt16[o + 8]      = __float2half_rn(v2);
                    vt16[o + Tv + 8] = __float2half_rn(v3);
                }
            }
        }
    }
}

#define G_CMODE0 0
#define G_CMODE1 1

// ---------------------------------------------------------------------------
// fp16 causal flash attention, cp.async double-buffered fp16 K / V^T tiles.
// ---------------------------------------------------------------------------
#define AKS 72               // smem row stride (fp16)
#define AT_BYTES 9216        // 64 * 72 * 2
#define A_OFF_K 0                      // 2 stages
#define A_OFF_V (2 * AT_BYTES)         // 2 stages
#define A_SMEM  (4 * AT_BYTES)         // 36864

__global__ __launch_bounds__(256, 2)
void attn_mma(const __half* __restrict__ q16, const __half* __restrict__ k16,
              const __half* __restrict__ vt16, __half* __restrict__ y16) {
    extern __shared__ char sm[];
    const uint32_t sbase = smem_u32(sm);

    const int qt = (gridDim.x - 1) - blockIdx.x;   // heavy blocks first
    const int h  = blockIdx.y;
    const int b  = blockIdx.z;
    const int tid = threadIdx.x;
    const int wid = tid >> 5, lane = tid & 31;
    const int g = lane >> 2, tig = lane & 3;

    const int bRow = ((lane >> 4) * 8) + (lane & 7);
    const int bCol8 = ((lane >> 3) & 1) * 8;

    const int qr0 = qt * 128;
    const int row0 = qr0 + wid * 16 + g;
    const size_t qb  = (size_t)(b * Hv + h) * Tv * Dv;   // q16/k16 base
    const size_t vtb = (size_t)(b * Hv + h) * Dv * Tv;   // vt16 base

    // async-load fp16 K tile [64 x 64] and V^T tile [64(d) x 64(kv)] for block kvb
    auto load_kv = [&](int kvb, int s) {
        const int kv0 = kvb * 64;
        #pragma unroll
        for (int i = 0; i < 2; i++) {
            const int u = tid + i * 256;
            const int r = u >> 3, c8 = (u & 7) * 8;
            CP16(sbase + A_OFF_K + s * AT_BYTES + (uint32_t)(r * 144 + c8 * 2),
                 k16 + qb + (size_t)(kv0 + r) * Dv + c8);
            CP16(sbase + A_OFF_V + s * AT_BYTES + (uint32_t)(r * 144 + c8 * 2),
                 vt16 + vtb + (size_t)r * Tv + kv0 + c8);
        }
    };

    // Q fragments: direct fp16 loads (pre-scaled)
    uint32_t qh[4][4];
    #pragma unroll
    for (int ks = 0; ks < 4; ks++) {
        const int kc = ks * 16 + tig * 2;
        #pragma unroll
        for (int j = 0; j < 4; j++) {
            const int rr = (j & 1) ? row0 + 8 : row0;
            const int cc = kc + ((j >> 1) ? 8 : 0);
            qh[ks][j] = *(const uint32_t*)(q16 + qb + (size_t)rr * Dv + cc);
        }
    }

    float acc_o[8][4];
    #pragma unroll
    for (int nt = 0; nt < 8; nt++)
        #pragma unroll
        for (int j = 0; j < 4; j++) acc_o[nt][j] = 0.f;
    float m0 = -INFINITY, m1 = -INFINITY, l0 = 0.f, l1 = 0.f;

    const int nkv = (qr0 >> 6) + 2;
    load_kv(0, 0);
    CP_COMMIT();

    for (int kvb = 0; kvb < nkv; kvb++) {
        const int kv0 = kvb * 64;
        const int s = kvb & 1;
        if (kvb + 1 < nkv) {
            load_kv(kvb + 1, s ^ 1);
            CP_COMMIT();
            CP_WAIT1();
        } else {
            CP_WAIT0();
        }
        __syncthreads();

        if (kv0 <= qr0 + wid * 16 + 15) {
            const uint32_t kbase = sbase + A_OFF_K + s * AT_BYTES;
            const uint32_t vbase = sbase + A_OFF_V + s * AT_BYTES;
            float s_[8][4];
            #pragma unroll
            for (int nt = 0; nt < 8; nt++)
                #pragma unroll
                for (int j = 0; j < 4; j++) s_[nt][j] = 0.f;

            #pragma unroll
            for (int ks = 0; ks < 4; ks++) {
                const int kc = ks * 16;
                #pragma unroll
                for (int p = 0; p < 4; p++) {
                    uint32_t bfr[4];
                    ldsm4(bfr, kbase + ((p * 16 + bRow) * AKS + kc + bCol8) * 2);
                    mma16816(s_[2 * p],     qh[ks], bfr[0], bfr[1]);
                    mma16816(s_[2 * p + 1], qh[ks], bfr[2], bfr[3]);
                }
            }

            float rmax0 = -INFINITY, rmax1 = -INFINITY;
            #pragma unroll
            for (int nt = 0; nt < 8; nt++) {
                const int colb = kv0 + nt * 8 + tig * 2;
                #pragma unroll
                for (int j = 0; j < 2; j++) {
                    if (colb + j > row0)     s_[nt][j]     = -INFINITY;
                    if (colb + j > row0 + 8) s_[nt][2 + j] = -INFINITY;
                    rmax0 = fmaxf(rmax0, s_[nt][j]);
                    rmax1 = fmaxf(rmax1, s_[nt][2 + j]);
                }
            }
            rmax0 = fmaxf(rmax0, __shfl_xor_sync(0xffffffff, rmax0, 1));
            rmax0 = fmaxf(rmax0, __shfl_xor_sync(0xffffffff, rmax0, 2));
            rmax1 = fmaxf(rmax1, __shfl_xor_sync(0xffffffff, rmax1, 1));
            rmax1 = fmaxf(rmax1, __shfl_xor_sync(0xffffffff, rmax1, 2));

            const float mn0 = fmaxf(m0, rmax0);
            const float mn1 = fmaxf(m1, rmax1);
            const float cr0 = __expf(m0 - mn0);
            const float cr1 = __expf(m1 - mn1);
            l0 *= cr0; l1 *= cr1;
            #pragma unroll
            for (int nt = 0; nt < 8; nt++) {
                acc_o[nt][0] *= cr0; acc_o[nt][1] *= cr0;
                acc_o[nt][2] *= cr1; acc_o[nt][3] *= cr1;
            }
            m0 = mn0; m1 = mn1;

            uint32_t ph[4][4];
            float rs0 = 0.f, rs1 = 0.f;
            #pragma unroll
            for (int kt = 0; kt < 4; kt++) {
                float p00, p01, p10, p11;
                p00 = __expf(s_[2 * kt][0] - mn0);
                p01 = __expf(s_[2 * kt][1] - mn0);
                p10 = __expf(s_[2 * kt][2] - mn1);
                p11 = __expf(s_[2 * kt][3] - mn1);
                rs0 += p00 + p01; rs1 += p10 + p11;
                ph[kt][0] = pack_h(p00, p01);
                ph[kt][1] = pack_h(p10, p11);
                p00 = __expf(s_[2 * kt + 1][0] - mn0);
                p01 = __expf(s_[2 * kt + 1][1] - mn0);
                p10 = __expf(s_[2 * kt + 1][2] - mn1);
                p11 = __expf(s_[2 * kt + 1][3] - mn1);
                rs0 += p00 + p01; rs1 += p10 + p11;
                ph[kt][2] = pack_h(p00, p01);
                ph[kt][3] = pack_h(p10, p11);
            }
            rs0 += __shfl_xor_sync(0xffffffff, rs0, 1);
            rs0 += __shfl_xor_sync(0xffffffff, rs0, 2);
            rs1 += __shfl_xor_sync(0xffffffff, rs1, 1);
            rs1 += __shfl_xor_sync(0xffffffff, rs1, 2);
            l0 += rs0; l1 += rs1;

            #pragma unroll
            for (int kt = 0; kt < 4; kt++) {
                const int kc = kt * 16;
                #pragma unroll
                for (int p = 0; p < 4; p++) {
                    uint32_t bfr[4];
                    ldsm4(bfr, vbase + ((p * 16 + bRow) * AKS + kc + bCol8) * 2);
                    mma16816(acc_o[2 * p],     ph[kt], bfr[0], bfr[1]);
                    mma16816(acc_o[2 * p + 1], ph[kt], bfr[2], bfr[3]);
                }
            }
        }
        __syncthreads();
    }

    const float i0 = 1.f / l0, i1 = 1.f / l1;
    #pragma unroll
    for (int nt = 0; nt < 8; nt++) {
        const int d = nt * 8 + tig * 2;
        const size_t o0 = ((size_t)b * Tv + row0) * Cv + h * Dv + d;
        const size_t o1 = o0 + (size_t)8 * Cv;
        *(uint32_t*)(y16 + o0) = pack_h(acc_o[nt][0] * i0, acc_o[nt][1] * i0);
        *(uint32_t*)(y16 + o1) = pack_h(acc_o[nt][2] * i1, acc_o[nt][3] * i1);
    }
}

// ---------------------------------------------------------------------------
extern "C" void kernel_launch(void* const* d_in, const int* in_sizes, int n_in,
                              void* d_out, int out_size) {
    const float* x      = (const float*)d_in[0];
    const float* w_attn = (const float*)d_in[1];
    const float* b_attn = (const float*)d_in[2];
    const float* w_proj = (const float*)d_in[3];
    const float* b_proj = (const float*)d_in[4];
    float* out = (float*)d_out;

    __half *x16, *wA, *wP, *q16, *k16, *vt16, *y16;
    cudaGetSymbolAddress((void**)&x16, g_x16);
    cudaGetSymbolAddress((void**)&wA, g_wA);
    cudaGetSymbolAddress((void**)&wP, g_wP);
    cudaGetSymbolAddress((void**)&q16, g_q16);
    cudaGetSymbolAddress((void**)&k16, g_k16);
    cudaGetSymbolAddress((void**)&vt16, g_vt16);
    cudaGetSymbolAddress((void**)&y16, g_y16);

    cudaFuncSetAttribute(gemm_mma<0>, cudaFuncAttributeMaxDynamicSharedMemorySize, G_SMEM);
    cudaFuncSetAttribute(gemm_mma<1>, cudaFuncAttributeMaxDynamicSharedMemorySize, G_SMEM);
    cudaFuncSetAttribute(attn_mma, cudaFuncAttributeMaxDynamicSharedMemorySize, A_SMEM);

    const int nx = Mv * Cv;
    cvt_kernel<<<(nx / 4 + 255) / 256, 256>>>(x, x16, nx);
    transpose_cvt<<<dim3(C3v / 32, Cv / 32), dim3(32, 8)>>>(w_attn, wA, Cv, C3v);
    transpose_cvt<<<dim3(Cv / 32, Cv / 32), dim3(32, 8)>>>(w_proj, wP, Cv, Cv);

    // 1) QKV GEMM with fused scatter epilogue -> q16 (scaled), k16, vt16
    gemm_mma<1><<<dim3(C3v / 64, Mv / 128), 256, G_SMEM>>>(
        x16, wA, b_attn, nullptr, q16, k16, vt16, C3v, Cv);
    // 2) causal flash attention (all-fp16 operands, cp.async pipelined)
    attn_mma<<<dim3(Tv / 128, Hv, Bv), 256, A_SMEM>>>(q16, k16, vt16, y16);
    // 3) out = y @ w_proj + b_proj (fp32 out)
    gemm_mma<0><<<dim3(Cv / 64, Mv / 128), 256, G_SMEM>>>(
        y16, wP, b_proj, out, nullptr, nullptr, nullptr, Cv, Cv);
}